// round 1
// baseline (speedup 1.0000x reference)
#include <cuda_runtime.h>
#include <math.h>

// Problem constants (fixed by setup_inputs)
#define BATCH 4
#define SEQ   2048
#define DMODEL 1024
#define NHEAD 16
#define DHEAD 64
#define BHD   (BATCH * NHEAD)          // 64
#define MTOT  (BATCH * SEQ)            // 8192
#define NQKV  (3 * DMODEL)             // 3072

// Scratch (sanctioned: __device__ globals, no runtime allocation)
__device__ float g_q[BHD * SEQ * DHEAD];   // [b,h,s,dh]
__device__ float g_k[BHD * SEQ * DHEAD];
__device__ float g_v[BHD * SEQ * DHEAD];
__device__ float g_o[BHD * SEQ * DHEAD];

// ---------------------------------------------------------------------------
// GEMM1: qkv = x @ w_qkv^T, scattered directly into per-head q/k/v layout.
// C[M=8192, N=3072] = A[M,1024] * W[N,1024]^T  (both K-contiguous, "NT")
// 128x128 block tile, BK=16, 256 threads, 8x8 per thread.
// ---------------------------------------------------------------------------
__global__ __launch_bounds__(256) void qkv_gemm_kernel(
    const float* __restrict__ A, const float* __restrict__ W)
{
    __shared__ float As[16][128];
    __shared__ float Bs[16][128];
    const int bm = blockIdx.y * 128;
    const int bn = blockIdx.x * 128;
    const int tid = threadIdx.x;
    const int tx = tid & 15;
    const int ty = tid >> 4;
    const int lr = tid >> 2;            // 0..63
    const int lc = (tid & 3) << 2;      // 0,4,8,12

    float acc[8][8];
#pragma unroll
    for (int i = 0; i < 8; i++)
#pragma unroll
        for (int j = 0; j < 8; j++) acc[i][j] = 0.f;

    const float* Ap = A + (bm + lr) * DMODEL + lc;
    const float* Wp = W + (bn + lr) * DMODEL + lc;

    for (int k0 = 0; k0 < DMODEL; k0 += 16) {
        float4 a0 = *(const float4*)(Ap + k0);
        float4 a1 = *(const float4*)(Ap + 64 * DMODEL + k0);
        float4 b0 = *(const float4*)(Wp + k0);
        float4 b1 = *(const float4*)(Wp + 64 * DMODEL + k0);
        As[lc+0][lr]    = a0.x; As[lc+1][lr]    = a0.y; As[lc+2][lr]    = a0.z; As[lc+3][lr]    = a0.w;
        As[lc+0][lr+64] = a1.x; As[lc+1][lr+64] = a1.y; As[lc+2][lr+64] = a1.z; As[lc+3][lr+64] = a1.w;
        Bs[lc+0][lr]    = b0.x; Bs[lc+1][lr]    = b0.y; Bs[lc+2][lr]    = b0.z; Bs[lc+3][lr]    = b0.w;
        Bs[lc+0][lr+64] = b1.x; Bs[lc+1][lr+64] = b1.y; Bs[lc+2][lr+64] = b1.z; Bs[lc+3][lr+64] = b1.w;
        __syncthreads();
#pragma unroll
        for (int kk = 0; kk < 16; kk++) {
            float4 af0 = *(const float4*)&As[kk][ty * 8];
            float4 af1 = *(const float4*)&As[kk][ty * 8 + 4];
            float4 bf0 = *(const float4*)&Bs[kk][tx * 8];
            float4 bf1 = *(const float4*)&Bs[kk][tx * 8 + 4];
            float ar[8] = {af0.x, af0.y, af0.z, af0.w, af1.x, af1.y, af1.z, af1.w};
            float br[8] = {bf0.x, bf0.y, bf0.z, bf0.w, bf1.x, bf1.y, bf1.z, bf1.w};
#pragma unroll
            for (int i = 0; i < 8; i++)
#pragma unroll
                for (int j = 0; j < 8; j++)
                    acc[i][j] += ar[i] * br[j];
        }
        __syncthreads();
    }

    // Epilogue: scatter to q/k/v in [b,h,s,dh] layout
#pragma unroll
    for (int i = 0; i < 8; i++) {
        const int m  = bm + ty * 8 + i;
        const int bb = m >> 11;           // / SEQ
        const int ss = m & (SEQ - 1);
#pragma unroll
        for (int j = 0; j < 8; j++) {
            const int n   = bn + tx * 8 + j;
            const int sec = n >> 10;                  // 0=q 1=k 2=v
            const int e   = n & (DMODEL - 1);
            const int h   = e >> 6;
            const int dh  = e & 63;
            float* dst = (sec == 0) ? g_q : (sec == 1 ? g_k : g_v);
            dst[((bb * NHEAD + h) * SEQ + ss) * DHEAD + dh] = acc[i][j];
        }
    }
}

// ---------------------------------------------------------------------------
// Attention: flash-style online softmax over a Gaussian-banded key window.
// Block: 64 queries of one (b,h); key tiles of 32. 256 threads (16x16 grid,
// each thread: 4 q-rows x 2 k-cols for scores, 4 q-rows x 4 d-cols for output).
// ---------------------------------------------------------------------------
__global__ __launch_bounds__(256) void attn_kernel(
    const int* __restrict__ mask, const int* __restrict__ use_g_p,
    const float* __restrict__ shift_p, const float* __restrict__ bias_pp)
{
    __shared__ float Qt[DHEAD][64];   // [d][r]
    __shared__ float Kt[DHEAD][32];   // [d][c]
    __shared__ float Vs[32][DHEAD];   // [c][d]
    __shared__ float Pt[32][65];      // [c][r], padded (2-way store conflicts max)
    __shared__ float msk[32];

    const int bh = blockIdx.y;        // b*NHEAD + h
    const int bb = bh >> 4;
    const int q0 = blockIdx.x * 64;
    const int tid = threadIdx.x;
    const int tx = tid & 15;
    const int ty = tid >> 4;

    const float shift = shift_p[0];
    const float biasv = bias_pp[0];
    const int   useg  = use_g_p[0];
    const float sh_eff = useg ? shift : 0.f;
    const float b_eff  = useg ? biasv : 0.f;

    int klo = 0, khi = SEQ;
    if (useg) {
        // Window: sqrt(100/shift) softmax decay + 64 masked-run slack + round-up
        const int Wi = (int)sqrtf(100.f / shift) + 66;
        klo = q0 - Wi;       if (klo < 0)   klo = 0;   klo &= ~31;
        khi = q0 + 64 + Wi;  if (khi > SEQ) khi = SEQ; khi = (khi + 31) & ~31;
        if (khi > SEQ) khi = SEQ;
    }

    // Load Q tile transposed: Qt[d][r]
    {
        const float* qp = g_q + (bh * SEQ + q0) * DHEAD;
        const int r  = tid & 63;
        const int u0 = tid >> 6;    // 0..3
#pragma unroll
        for (int u = u0; u < 16; u += 4) {
            float4 qv = *(const float4*)(qp + r * DHEAD + u * 4);
            Qt[u*4+0][r] = qv.x; Qt[u*4+1][r] = qv.y;
            Qt[u*4+2][r] = qv.z; Qt[u*4+3][r] = qv.w;
        }
    }

    float m_i[4], l_i[4], oacc[4][4];
#pragma unroll
    for (int i = 0; i < 4; i++) {
        m_i[i] = -1e30f; l_i[i] = 0.f;
#pragma unroll
        for (int j = 0; j < 4; j++) oacc[i][j] = 0.f;
    }

    const float* kbase = g_k + bh * SEQ * DHEAD;
    const float* vbase = g_v + bh * SEQ * DHEAD;
    const int*   mbase = mask + bb * SEQ;

    for (int kt = klo; kt < khi; kt += 32) {
        __syncthreads();   // prior tile fully consumed (Kt scores, Pt/Vs in PV)
        // Load K transposed
        {
            const int c  = tid & 31;
            const int u0 = tid >> 5;   // 0..7
            const float* kp = kbase + (kt + c) * DHEAD;
#pragma unroll
            for (int u = u0; u < 16; u += 8) {
                float4 kv = *(const float4*)(kp + u * 4);
                Kt[u*4+0][c] = kv.x; Kt[u*4+1][c] = kv.y;
                Kt[u*4+2][c] = kv.z; Kt[u*4+3][c] = kv.w;
            }
        }
        // Load V natural layout (coalesced)
        {
            int f = tid;
#pragma unroll
            for (int it = 0; it < 2; it++, f += 256) {
                const int r  = f >> 4;
                const int cc = (f & 15) << 2;
                *(float4*)&Vs[r][cc] = *(const float4*)(vbase + (kt + r) * DHEAD + cc);
            }
        }
        if (tid < 32) msk[tid] = (mbase[kt + tid] != 0) ? 0.f : -1e30f;
        __syncthreads();

        // Scores: 4 rows x 2 cols per thread
        float sacc[4][2];
#pragma unroll
        for (int i = 0; i < 4; i++) { sacc[i][0] = 0.f; sacc[i][1] = 0.f; }
#pragma unroll
        for (int d = 0; d < DHEAD; d++) {
            float4 aq = *(const float4*)&Qt[d][ty * 4];
            float2 ak = *(const float2*)&Kt[d][tx * 2];
            sacc[0][0] += aq.x * ak.x; sacc[0][1] += aq.x * ak.y;
            sacc[1][0] += aq.y * ak.x; sacc[1][1] += aq.y * ak.y;
            sacc[2][0] += aq.z * ak.x; sacc[2][1] += aq.z * ak.y;
            sacc[3][0] += aq.w * ak.x; sacc[3][1] += aq.w * ak.y;
        }
        // Logits: scale, key mask, Gaussian distance bias
#pragma unroll
        for (int i = 0; i < 4; i++) {
            const int qi = q0 + ty * 4 + i;
#pragma unroll
            for (int j = 0; j < 2; j++) {
                const int kj = kt + tx * 2 + j;
                const float dd = (float)(qi - kj);
                sacc[i][j] = sacc[i][j] * 0.125f + msk[tx*2+j] - (sh_eff * dd * dd + b_eff);
            }
        }
        // Online softmax (row groups = 16 consecutive lanes, same ty)
#pragma unroll
        for (int i = 0; i < 4; i++) {
            float mx = fmaxf(sacc[i][0], sacc[i][1]);
#pragma unroll
            for (int off = 8; off > 0; off >>= 1)
                mx = fmaxf(mx, __shfl_xor_sync(0xffffffffu, mx, off));
            const float mnew = fmaxf(m_i[i], mx);
            const float corr = __expf(m_i[i] - mnew);
            m_i[i] = mnew;
            float rs = 0.f;
#pragma unroll
            for (int j = 0; j < 2; j++) {
                const float p = __expf(sacc[i][j] - mnew);
                sacc[i][j] = p;
                rs += p;
            }
#pragma unroll
            for (int off = 8; off > 0; off >>= 1)
                rs += __shfl_xor_sync(0xffffffffu, rs, off);
            l_i[i] = l_i[i] * corr + rs;
#pragma unroll
            for (int j = 0; j < 4; j++) oacc[i][j] *= corr;
        }
        // Write P^T to shared
#pragma unroll
        for (int i = 0; i < 4; i++)
#pragma unroll
            for (int j = 0; j < 2; j++)
                Pt[tx*2+j][ty*4+i] = sacc[i][j];
        __syncthreads();
        // PV: oacc[r][dcol] += P[r][c] * V[c][dcol]
#pragma unroll
        for (int c = 0; c < 32; c++) {
            const float pa0 = Pt[c][ty*4+0];
            const float pa1 = Pt[c][ty*4+1];
            const float pa2 = Pt[c][ty*4+2];
            const float pa3 = Pt[c][ty*4+3];
            float4 bv = *(const float4*)&Vs[c][tx * 4];
            oacc[0][0] += pa0*bv.x; oacc[0][1] += pa0*bv.y; oacc[0][2] += pa0*bv.z; oacc[0][3] += pa0*bv.w;
            oacc[1][0] += pa1*bv.x; oacc[1][1] += pa1*bv.y; oacc[1][2] += pa1*bv.z; oacc[1][3] += pa1*bv.w;
            oacc[2][0] += pa2*bv.x; oacc[2][1] += pa2*bv.y; oacc[2][2] += pa2*bv.z; oacc[2][3] += pa2*bv.w;
            oacc[3][0] += pa3*bv.x; oacc[3][1] += pa3*bv.y; oacc[3][2] += pa3*bv.z; oacc[3][3] += pa3*bv.w;
        }
    }

    // Normalize and write O
    float* op = g_o + (bh * SEQ + q0) * DHEAD;
#pragma unroll
    for (int i = 0; i < 4; i++) {
        const float inv = 1.f / l_i[i];
        float4 ov;
        ov.x = oacc[i][0] * inv; ov.y = oacc[i][1] * inv;
        ov.z = oacc[i][2] * inv; ov.w = oacc[i][3] * inv;
        *(float4*)(op + (ty * 4 + i) * DHEAD + tx * 4) = ov;
    }
}

// ---------------------------------------------------------------------------
// GEMM2: out = O @ w_fc^T + b_fc ; O read from [b,h,s,dh] layout via index map
// ---------------------------------------------------------------------------
__global__ __launch_bounds__(256) void proj_gemm_kernel(
    const float* __restrict__ W, const float* __restrict__ bias,
    float* __restrict__ Y)
{
    __shared__ float As[16][128];
    __shared__ float Bs[16][128];
    const int bm = blockIdx.y * 128;
    const int bn = blockIdx.x * 128;
    const int tid = threadIdx.x;
    const int tx = tid & 15;
    const int ty = tid >> 4;
    const int lr = tid >> 2;
    const int lc = (tid & 3) << 2;

    float acc[8][8];
#pragma unroll
    for (int i = 0; i < 8; i++)
#pragma unroll
        for (int j = 0; j < 8; j++) acc[i][j] = 0.f;

    const float* Wp = W + (bn + lr) * DMODEL + lc;
    const int m0 = bm + lr;
    const int b0 = m0 >> 11, s0 = m0 & (SEQ - 1);
    const int m1 = m0 + 64;
    const int b1 = m1 >> 11, s1 = m1 & (SEQ - 1);

    for (int k0 = 0; k0 < DMODEL; k0 += 16) {
        const int kc = k0 + lc;
        const int h  = kc >> 6;
        const int dh = kc & 63;
        float4 a0 = *(const float4*)(g_o + ((b0 * NHEAD + h) * SEQ + s0) * DHEAD + dh);
        float4 a1 = *(const float4*)(g_o + ((b1 * NHEAD + h) * SEQ + s1) * DHEAD + dh);
        float4 b0v = *(const float4*)(Wp + k0);
        float4 b1v = *(const float4*)(Wp + 64 * DMODEL + k0);
        As[lc+0][lr]    = a0.x; As[lc+1][lr]    = a0.y; As[lc+2][lr]    = a0.z; As[lc+3][lr]    = a0.w;
        As[lc+0][lr+64] = a1.x; As[lc+1][lr+64] = a1.y; As[lc+2][lr+64] = a1.z; As[lc+3][lr+64] = a1.w;
        Bs[lc+0][lr]    = b0v.x; Bs[lc+1][lr]    = b0v.y; Bs[lc+2][lr]    = b0v.z; Bs[lc+3][lr]    = b0v.w;
        Bs[lc+0][lr+64] = b1v.x; Bs[lc+1][lr+64] = b1v.y; Bs[lc+2][lr+64] = b1v.z; Bs[lc+3][lr+64] = b1v.w;
        __syncthreads();
#pragma unroll
        for (int kk = 0; kk < 16; kk++) {
            float4 af0 = *(const float4*)&As[kk][ty * 8];
            float4 af1 = *(const float4*)&As[kk][ty * 8 + 4];
            float4 bf0 = *(const float4*)&Bs[kk][tx * 8];
            float4 bf1 = *(const float4*)&Bs[kk][tx * 8 + 4];
            float ar[8] = {af0.x, af0.y, af0.z, af0.w, af1.x, af1.y, af1.z, af1.w};
            float br[8] = {bf0.x, bf0.y, bf0.z, bf0.w, bf1.x, bf1.y, bf1.z, bf1.w};
#pragma unroll
            for (int i = 0; i < 8; i++)
#pragma unroll
                for (int j = 0; j < 8; j++)
                    acc[i][j] += ar[i] * br[j];
        }
        __syncthreads();
    }

    const int n0 = bn + tx * 8;
    float4 bia0 = *(const float4*)(bias + n0);
    float4 bia1 = *(const float4*)(bias + n0 + 4);
#pragma unroll
    for (int i = 0; i < 8; i++) {
        const int m = bm + ty * 8 + i;
        float4 y0, y1;
        y0.x = acc[i][0] + bia0.x; y0.y = acc[i][1] + bia0.y;
        y0.z = acc[i][2] + bia0.z; y0.w = acc[i][3] + bia0.w;
        y1.x = acc[i][4] + bia1.x; y1.y = acc[i][5] + bia1.y;
        y1.z = acc[i][6] + bia1.z; y1.w = acc[i][7] + bia1.w;
        *(float4*)(Y + m * DMODEL + n0)     = y0;
        *(float4*)(Y + m * DMODEL + n0 + 4) = y1;
    }
}

// ---------------------------------------------------------------------------
extern "C" void kernel_launch(void* const* d_in, const int* in_sizes, int n_in,
                              void* d_out, int out_size)
{
    const float* x      = (const float*)d_in[0];
    const int*   mask   = (const int*)  d_in[1];
    // d_in[2] = qmask (unused by reference)
    const int*   useg   = (const int*)  d_in[3];
    const float* w_qkv  = (const float*)d_in[4];
    const float* w_fc   = (const float*)d_in[5];
    const float* b_fc   = (const float*)d_in[6];
    const float* shift  = (const float*)d_in[7];
    const float* bias_p = (const float*)d_in[8];
    float* out = (float*)d_out;

    qkv_gemm_kernel<<<dim3(NQKV / 128, MTOT / 128), 256>>>(x, w_qkv);
    attn_kernel   <<<dim3(SEQ / 64, BHD),          256>>>(mask, useg, shift, bias_p);
    proj_gemm_kernel<<<dim3(DMODEL / 128, MTOT / 128), 256>>>(w_fc, b_fc, out);
}

// round 3
// speedup vs baseline: 2.2496x; 2.2496x over previous
#include <cuda_runtime.h>
#include <cuda_bf16.h>
#include <math.h>
#include <stdint.h>

// Problem constants (fixed by setup_inputs)
#define BATCH 4
#define SEQ   2048
#define DMODEL 1024
#define NHEAD 16
#define DHEAD 64
#define BHD   (BATCH * NHEAD)          // 64
#define MTOT  (BATCH * SEQ)            // 8192
#define NQKV  (3 * DMODEL)             // 3072

// Scratch (sanctioned: __device__ globals, no runtime allocation)
__device__ float g_q[BHD * SEQ * DHEAD];   // [b,h,s,dh]
__device__ float g_k[BHD * SEQ * DHEAD];
__device__ float g_v[BHD * SEQ * DHEAD];
__device__ float g_o[BHD * SEQ * DHEAD];

// ---------------------------------------------------------------------------
// Baseline-PTX tensor core helpers (compute_80-era: safe for plain sm_103)
// ---------------------------------------------------------------------------
__device__ __forceinline__ uint32_t smem_u32(const void* p) {
    uint32_t a;
    asm("{ .reg .u64 t; cvta.to.shared.u64 t, %1; cvt.u32.u64 %0, t; }"
        : "=r"(a) : "l"(p));
    return a;
}

#define LDSM_X4(r0, r1, r2, r3, addr)                                       \
    asm volatile("ldmatrix.sync.aligned.m8n8.x4.shared.b16 {%0,%1,%2,%3}, [%4];" \
                 : "=r"(r0), "=r"(r1), "=r"(r2), "=r"(r3) : "r"(addr))

__device__ __forceinline__ void mma_bf16(float* d, const uint32_t* a,
                                         uint32_t b0, uint32_t b1) {
    asm volatile(
        "mma.sync.aligned.m16n8k16.row.col.f32.bf16.bf16.f32 "
        "{%0,%1,%2,%3}, {%4,%5,%6,%7}, {%8,%9}, {%0,%1,%2,%3};"
        : "+f"(d[0]), "+f"(d[1]), "+f"(d[2]), "+f"(d[3])
        : "r"(a[0]), "r"(a[1]), "r"(a[2]), "r"(a[3]), "r"(b0), "r"(b1));
}

// ---------------------------------------------------------------------------
// bf16x3 GEMM via mma.sync. 128x128 CTA tile, 8 warps (64x32 warp tiles),
// K-chunk 32, double-buffered SMEM, register prefetch of next chunk.
// SMEM tile layout: [128 rows][40 halves] (80B pitch -> conflict-free ldmatrix)
// Stage = Ah | Al | Bh | Bl, each 128*40*2 = 10240 B.
// mode 0: C = x @ w_qkv^T, scatter into g_q/g_k/g_v [b,h,s,dh]
// mode 1: C = O @ w_fc^T + b_fc, O gathered from g_o, write out
// ---------------------------------------------------------------------------
#define KCH        32
#define NCH        (DMODEL / KCH)   // 32
#define PITCH_H    40               // halves per row
#define TILE_B     (128 * PITCH_H * 2)   // 10240
#define STAGE_B    (4 * TILE_B)          // 40960
#define DSMEM_BYTES (2 * STAGE_B)        // 81920

__device__ __forceinline__ void split4(float4 v, uint2& hi, uint2& lo) {
    __nv_bfloat162 h01 = __floats2bfloat162_rn(v.x, v.y);
    __nv_bfloat162 h23 = __floats2bfloat162_rn(v.z, v.w);
    __nv_bfloat162 l01 = __floats2bfloat162_rn(v.x - __bfloat162float(h01.x),
                                               v.y - __bfloat162float(h01.y));
    __nv_bfloat162 l23 = __floats2bfloat162_rn(v.z - __bfloat162float(h23.x),
                                               v.w - __bfloat162float(h23.y));
    hi.x = *(uint32_t*)&h01; hi.y = *(uint32_t*)&h23;
    lo.x = *(uint32_t*)&l01; lo.y = *(uint32_t*)&l23;
}

__global__ __launch_bounds__(256) void gemm_bf16x3_kernel(
    const float* __restrict__ A, const float* __restrict__ W,
    const float* __restrict__ bias, float* __restrict__ out, int mode)
{
    extern __shared__ __align__(128) char dsm[];
    const uint32_t sbase = smem_u32(dsm);

    const int tid  = threadIdx.x;
    const int lane = tid & 31;
    const int warp = tid >> 5;
    const int bm = blockIdx.y * 128;
    const int bn = blockIdx.x * 128;
    const int warp_m = (warp >> 2) << 6;   // 0 or 64
    const int warp_n = (warp & 3) << 5;    // 0,32,64,96

    // loader indices: each thread handles 4 rows (p*32 + tid>>3), 1 float4 each
    const int lrow = tid >> 3;   // 0..31
    const int lc4  = tid & 7;    // float4 index within 32-col chunk

    float acc[4][4][4];
#pragma unroll
    for (int i = 0; i < 4; i++)
#pragma unroll
        for (int j = 0; j < 4; j++)
#pragma unroll
            for (int r = 0; r < 4; r++) acc[i][j][r] = 0.f;

    float4 av[4], wv[4];

    // ---- global load of chunk c into registers ----
    auto load_chunk = [&](int c) {
#pragma unroll
        for (int p = 0; p < 4; ++p) {
            const int row = lrow + (p << 5);
            const int k   = (c << 5) + (lc4 << 2);
            const float* ap;
            if (mode == 0) {
                ap = A + (bm + row) * DMODEL + k;
            } else {
                const int m = bm + row;
                ap = g_o + ((((m >> 11) << 4) + (k >> 6)) * SEQ + (m & (SEQ - 1))) * DHEAD
                     + (k & 63);
            }
            av[p] = *(const float4*)ap;
            wv[p] = *(const float4*)(W + (bn + row) * DMODEL + k);
        }
    };

    // ---- convert regs -> smem stage st ----
    auto store_chunk = [&](int st) {
        char* base = dsm + st * STAGE_B;
#pragma unroll
        for (int p = 0; p < 4; ++p) {
            const int row = lrow + (p << 5);
            const uint32_t off = row * (PITCH_H * 2) + (lc4 << 3);   // bytes
            uint2 hi, lo;
            split4(av[p], hi, lo);
            *(uint2*)(base + off)              = hi;
            *(uint2*)(base + TILE_B + off)     = lo;
            split4(wv[p], hi, lo);
            *(uint2*)(base + 2 * TILE_B + off) = hi;
            *(uint2*)(base + 3 * TILE_B + off) = lo;
        }
    };

    load_chunk(0);
    store_chunk(0);
    __syncthreads();

    const uint32_t lrow16 = lane & 15;
    const uint32_t lcol16 = (lane >> 4) << 4;   // 0 or 16 bytes

    for (int c = 0; c < NCH; ++c) {
        const int st = c & 1;
        if (c + 1 < NCH) load_chunk(c + 1);

        const uint32_t sa = sbase + st * STAGE_B;
        const uint32_t sb = sa + 2 * TILE_B;

#pragma unroll
        for (int kh = 0; kh < 2; ++kh) {
            uint32_t ah[4][4], al[4][4], bh[4][2], bl[4][2];
#pragma unroll
            for (int mi = 0; mi < 4; ++mi) {
                const uint32_t ad = sa + (warp_m + (mi << 4) + lrow16) * (PITCH_H * 2)
                                    + (kh << 5) + lcol16;
                LDSM_X4(ah[mi][0], ah[mi][1], ah[mi][2], ah[mi][3], ad);
                LDSM_X4(al[mi][0], al[mi][1], al[mi][2], al[mi][3], ad + TILE_B);
            }
#pragma unroll
            for (int g = 0; g < 2; ++g) {
                const uint32_t bd = sb + (warp_n + (g << 4) + lrow16) * (PITCH_H * 2)
                                    + (kh << 5) + lcol16;
                uint32_t t0, t1, t2, t3;
                LDSM_X4(t0, t1, t2, t3, bd);
                bh[g * 2][0] = t0; bh[g * 2][1] = t2;
                bh[g * 2 + 1][0] = t1; bh[g * 2 + 1][1] = t3;
                LDSM_X4(t0, t1, t2, t3, bd + TILE_B);
                bl[g * 2][0] = t0; bl[g * 2][1] = t2;
                bl[g * 2 + 1][0] = t1; bl[g * 2 + 1][1] = t3;
            }
#pragma unroll
            for (int mi = 0; mi < 4; ++mi)
#pragma unroll
                for (int nj = 0; nj < 4; ++nj) {
                    mma_bf16(acc[mi][nj], ah[mi], bh[nj][0], bh[nj][1]);
                    mma_bf16(acc[mi][nj], ah[mi], bl[nj][0], bl[nj][1]);
                    mma_bf16(acc[mi][nj], al[mi], bh[nj][0], bh[nj][1]);
                }
        }

        if (c + 1 < NCH) store_chunk(st ^ 1);
        __syncthreads();
    }

    // ---- epilogue ----
    const int er = lane >> 2;          // 0..7
    const int ec = (lane & 3) << 1;    // 0,2,4,6
#pragma unroll
    for (int mi = 0; mi < 4; ++mi) {
#pragma unroll
        for (int nj = 0; nj < 4; ++nj) {
            const int m = bm + warp_m + (mi << 4) + er;
            const int n = bn + warp_n + (nj << 3) + ec;
            if (mode == 0) {
                const int bb = m >> 11;
                const int ss = m & (SEQ - 1);
                const int sec = n >> 10;
                const int e = n & (DMODEL - 1);
                const int h = e >> 6;
                const int dh = e & 63;
                float* dst = (sec == 0 ? g_q : (sec == 1 ? g_k : g_v))
                             + ((bb * NHEAD + h) * SEQ + ss) * DHEAD + dh;
                *(float2*)dst = make_float2(acc[mi][nj][0], acc[mi][nj][1]);
                *(float2*)(dst + 8 * DHEAD) = make_float2(acc[mi][nj][2], acc[mi][nj][3]);
            } else {
                const float2 bv = *(const float2*)(bias + n);
                float* dst = out + m * DMODEL + n;
                *(float2*)dst = make_float2(acc[mi][nj][0] + bv.x, acc[mi][nj][1] + bv.y);
                *(float2*)(dst + 8 * DMODEL) =
                    make_float2(acc[mi][nj][2] + bv.x, acc[mi][nj][3] + bv.y);
            }
        }
    }
}

// ---------------------------------------------------------------------------
// Attention: flash-style online softmax over a Gaussian-banded key window.
// (unchanged — fp32 SIMT; passed round 1)
// ---------------------------------------------------------------------------
__global__ __launch_bounds__(256) void attn_kernel(
    const int* __restrict__ mask, const int* __restrict__ use_g_p,
    const float* __restrict__ shift_p, const float* __restrict__ bias_pp)
{
    __shared__ float Qt[DHEAD][64];
    __shared__ float Kt[DHEAD][32];
    __shared__ float Vs[32][DHEAD];
    __shared__ float Pt[32][65];
    __shared__ float msk[32];

    const int bh = blockIdx.y;
    const int bb = bh >> 4;
    const int q0 = blockIdx.x * 64;
    const int tid = threadIdx.x;
    const int tx = tid & 15;
    const int ty = tid >> 4;

    const float shift = shift_p[0];
    const float biasv = bias_pp[0];
    const int   useg  = use_g_p[0];
    const float sh_eff = useg ? shift : 0.f;
    const float b_eff  = useg ? biasv : 0.f;

    int klo = 0, khi = SEQ;
    if (useg) {
        const int Wi = (int)sqrtf(100.f / shift) + 66;
        klo = q0 - Wi;       if (klo < 0)   klo = 0;   klo &= ~31;
        khi = q0 + 64 + Wi;  if (khi > SEQ) khi = SEQ; khi = (khi + 31) & ~31;
        if (khi > SEQ) khi = SEQ;
    }

    {
        const float* qp = g_q + (bh * SEQ + q0) * DHEAD;
        const int r  = tid & 63;
        const int u0 = tid >> 6;
#pragma unroll
        for (int u = u0; u < 16; u += 4) {
            float4 qv = *(const float4*)(qp + r * DHEAD + u * 4);
            Qt[u*4+0][r] = qv.x; Qt[u*4+1][r] = qv.y;
            Qt[u*4+2][r] = qv.z; Qt[u*4+3][r] = qv.w;
        }
    }

    float m_i[4], l_i[4], oacc[4][4];
#pragma unroll
    for (int i = 0; i < 4; i++) {
        m_i[i] = -1e30f; l_i[i] = 0.f;
#pragma unroll
        for (int j = 0; j < 4; j++) oacc[i][j] = 0.f;
    }

    const float* kbase = g_k + bh * SEQ * DHEAD;
    const float* vbase = g_v + bh * SEQ * DHEAD;
    const int*   mbase = mask + bb * SEQ;

    for (int kt = klo; kt < khi; kt += 32) {
        __syncthreads();
        {
            const int c  = tid & 31;
            const int u0 = tid >> 5;
            const float* kp = kbase + (kt + c) * DHEAD;
#pragma unroll
            for (int u = u0; u < 16; u += 8) {
                float4 kv = *(const float4*)(kp + u * 4);
                Kt[u*4+0][c] = kv.x; Kt[u*4+1][c] = kv.y;
                Kt[u*4+2][c] = kv.z; Kt[u*4+3][c] = kv.w;
            }
        }
        {
            int f = tid;
#pragma unroll
            for (int it = 0; it < 2; it++, f += 256) {
                const int r  = f >> 4;
                const int cc = (f & 15) << 2;
                *(float4*)&Vs[r][cc] = *(const float4*)(vbase + (kt + r) * DHEAD + cc);
            }
        }
        if (tid < 32) msk[tid] = (mbase[kt + tid] != 0) ? 0.f : -1e30f;
        __syncthreads();

        float sacc[4][2];
#pragma unroll
        for (int i = 0; i < 4; i++) { sacc[i][0] = 0.f; sacc[i][1] = 0.f; }
#pragma unroll
        for (int d = 0; d < DHEAD; d++) {
            float4 aq = *(const float4*)&Qt[d][ty * 4];
            float2 ak = *(const float2*)&Kt[d][tx * 2];
            sacc[0][0] += aq.x * ak.x; sacc[0][1] += aq.x * ak.y;
            sacc[1][0] += aq.y * ak.x; sacc[1][1] += aq.y * ak.y;
            sacc[2][0] += aq.z * ak.x; sacc[2][1] += aq.z * ak.y;
            sacc[3][0] += aq.w * ak.x; sacc[3][1] += aq.w * ak.y;
        }
#pragma unroll
        for (int i = 0; i < 4; i++) {
            const int qi = q0 + ty * 4 + i;
#pragma unroll
            for (int j = 0; j < 2; j++) {
                const int kj = kt + tx * 2 + j;
                const float dd = (float)(qi - kj);
                sacc[i][j] = sacc[i][j] * 0.125f + msk[tx*2+j] - (sh_eff * dd * dd + b_eff);
            }
        }
#pragma unroll
        for (int i = 0; i < 4; i++) {
            float mx = fmaxf(sacc[i][0], sacc[i][1]);
#pragma unroll
            for (int off = 8; off > 0; off >>= 1)
                mx = fmaxf(mx, __shfl_xor_sync(0xffffffffu, mx, off));
            const float mnew = fmaxf(m_i[i], mx);
            const float corr = __expf(m_i[i] - mnew);
            m_i[i] = mnew;
            float rs = 0.f;
#pragma unroll
            for (int j = 0; j < 2; j++) {
                const float p = __expf(sacc[i][j] - mnew);
                sacc[i][j] = p;
                rs += p;
            }
#pragma unroll
            for (int off = 8; off > 0; off >>= 1)
                rs += __shfl_xor_sync(0xffffffffu, rs, off);
            l_i[i] = l_i[i] * corr + rs;
#pragma unroll
            for (int j = 0; j < 4; j++) oacc[i][j] *= corr;
        }
#pragma unroll
        for (int i = 0; i < 4; i++)
#pragma unroll
            for (int j = 0; j < 2; j++)
                Pt[tx*2+j][ty*4+i] = sacc[i][j];
        __syncthreads();
#pragma unroll
        for (int c = 0; c < 32; c++) {
            const float pa0 = Pt[c][ty*4+0];
            const float pa1 = Pt[c][ty*4+1];
            const float pa2 = Pt[c][ty*4+2];
            const float pa3 = Pt[c][ty*4+3];
            float4 bv = *(const float4*)&Vs[c][tx * 4];
            oacc[0][0] += pa0*bv.x; oacc[0][1] += pa0*bv.y; oacc[0][2] += pa0*bv.z; oacc[0][3] += pa0*bv.w;
            oacc[1][0] += pa1*bv.x; oacc[1][1] += pa1*bv.y; oacc[1][2] += pa1*bv.z; oacc[1][3] += pa1*bv.w;
            oacc[2][0] += pa2*bv.x; oacc[2][1] += pa2*bv.y; oacc[2][2] += pa2*bv.z; oacc[2][3] += pa2*bv.w;
            oacc[3][0] += pa3*bv.x; oacc[3][1] += pa3*bv.y; oacc[3][2] += pa3*bv.z; oacc[3][3] += pa3*bv.w;
        }
    }

    float* op = g_o + (bh * SEQ + q0) * DHEAD;
#pragma unroll
    for (int i = 0; i < 4; i++) {
        const float inv = 1.f / l_i[i];
        float4 ov;
        ov.x = oacc[i][0] * inv; ov.y = oacc[i][1] * inv;
        ov.z = oacc[i][2] * inv; ov.w = oacc[i][3] * inv;
        *(float4*)(op + (ty * 4 + i) * DHEAD + tx * 4) = ov;
    }
}

// ---------------------------------------------------------------------------
extern "C" void kernel_launch(void* const* d_in, const int* in_sizes, int n_in,
                              void* d_out, int out_size)
{
    const float* x      = (const float*)d_in[0];
    const int*   mask   = (const int*)  d_in[1];
    // d_in[2] = qmask (unused by reference)
    const int*   useg   = (const int*)  d_in[3];
    const float* w_qkv  = (const float*)d_in[4];
    const float* w_fc   = (const float*)d_in[5];
    const float* b_fc   = (const float*)d_in[6];
    const float* shift  = (const float*)d_in[7];
    const float* bias_p = (const float*)d_in[8];
    float* out = (float*)d_out;

    static bool attr_set = false;
    if (!attr_set) {
        cudaFuncSetAttribute(gemm_bf16x3_kernel,
                             cudaFuncAttributeMaxDynamicSharedMemorySize, DSMEM_BYTES);
        attr_set = true;
    }

    gemm_bf16x3_kernel<<<dim3(NQKV / 128, MTOT / 128), 256, DSMEM_BYTES>>>(
        x, w_qkv, nullptr, nullptr, 0);
    attn_kernel<<<dim3(SEQ / 64, BHD), 256>>>(mask, useg, shift, bias_p);
    gemm_bf16x3_kernel<<<dim3(DMODEL / 128, MTOT / 128), 256, DSMEM_BYTES>>>(
        nullptr, w_fc, b_fc, out, 1);
}

// round 4
// speedup vs baseline: 2.3637x; 1.0507x over previous
#include <cuda_runtime.h>
#include <cuda_bf16.h>
#include <math.h>
#include <stdint.h>

// Problem constants (fixed by setup_inputs)
#define BATCH 4
#define SEQ   2048
#define DMODEL 1024
#define NHEAD 16
#define DHEAD 64
#define BHD   (BATCH * NHEAD)          // 64
#define MTOT  (BATCH * SEQ)            // 8192
#define NQKV  (3 * DMODEL)             // 3072

// Scratch (sanctioned: __device__ globals, no runtime allocation)
__device__ float g_q[BHD * SEQ * DHEAD];   // fp32 [b,h,s,dh] for attention
__device__ float g_k[BHD * SEQ * DHEAD];
__device__ float g_v[BHD * SEQ * DHEAD];

// Pre-split bf16 hi/lo operands
__device__ __align__(128) __nv_bfloat16 g_xh[MTOT * DMODEL];
__device__ __align__(128) __nv_bfloat16 g_xl[MTOT * DMODEL];
__device__ __align__(128) __nv_bfloat16 g_wqh[NQKV * DMODEL];
__device__ __align__(128) __nv_bfloat16 g_wql[NQKV * DMODEL];
__device__ __align__(128) __nv_bfloat16 g_wfh[DMODEL * DMODEL];
__device__ __align__(128) __nv_bfloat16 g_wfl[DMODEL * DMODEL];
__device__ __align__(128) __nv_bfloat16 g_ohi[BHD * SEQ * DHEAD];  // [b,h,s,dh]
__device__ __align__(128) __nv_bfloat16 g_olo[BHD * SEQ * DHEAD];

// ---------------------------------------------------------------------------
// helpers
// ---------------------------------------------------------------------------
__device__ __forceinline__ uint32_t smem_u32(const void* p) {
    uint32_t a;
    asm("{ .reg .u64 t; cvta.to.shared.u64 t, %1; cvt.u32.u64 %0, t; }"
        : "=r"(a) : "l"(p));
    return a;
}

#define LDSM_X4(r0, r1, r2, r3, addr)                                       \
    asm volatile("ldmatrix.sync.aligned.m8n8.x4.shared.b16 {%0,%1,%2,%3}, [%4];" \
                 : "=r"(r0), "=r"(r1), "=r"(r2), "=r"(r3) : "r"(addr))

__device__ __forceinline__ void mma_bf16(float* d, const uint32_t* a,
                                         uint32_t b0, uint32_t b1) {
    asm volatile(
        "mma.sync.aligned.m16n8k16.row.col.f32.bf16.bf16.f32 "
        "{%0,%1,%2,%3}, {%4,%5,%6,%7}, {%8,%9}, {%0,%1,%2,%3};"
        : "+f"(d[0]), "+f"(d[1]), "+f"(d[2]), "+f"(d[3])
        : "r"(a[0]), "r"(a[1]), "r"(a[2]), "r"(a[3]), "r"(b0), "r"(b1));
}

#define CP_ASYNC16(dst, src) \
    asm volatile("cp.async.cg.shared.global [%0], [%1], 16;" \
                 :: "r"(dst), "l"(src) : "memory")
#define CP_COMMIT()  asm volatile("cp.async.commit_group;" ::: "memory")
#define CP_WAIT(n)   asm volatile("cp.async.wait_group %0;" :: "n"(n) : "memory")

__device__ __forceinline__ void split4(float4 v, uint2& hi, uint2& lo) {
    __nv_bfloat162 h01 = __floats2bfloat162_rn(v.x, v.y);
    __nv_bfloat162 h23 = __floats2bfloat162_rn(v.z, v.w);
    __nv_bfloat162 l01 = __floats2bfloat162_rn(v.x - __bfloat162float(h01.x),
                                               v.y - __bfloat162float(h01.y));
    __nv_bfloat162 l23 = __floats2bfloat162_rn(v.z - __bfloat162float(h23.x),
                                               v.w - __bfloat162float(h23.y));
    hi.x = *(uint32_t*)&h01; hi.y = *(uint32_t*)&h23;
    lo.x = *(uint32_t*)&l01; lo.y = *(uint32_t*)&l23;
}

// ---------------------------------------------------------------------------
// Pre-pass: split fp32 array into bf16 hi/lo (bandwidth-bound, ~20us total)
// ---------------------------------------------------------------------------
__global__ __launch_bounds__(256) void split_kernel(
    const float4* __restrict__ src, uint2* __restrict__ hi,
    uint2* __restrict__ lo, int n4)
{
    for (int i = blockIdx.x * blockDim.x + threadIdx.x; i < n4;
         i += gridDim.x * blockDim.x) {
        uint2 h, l;
        split4(src[i], h, l);
        hi[i] = h;
        lo[i] = l;
    }
}

// ---------------------------------------------------------------------------
// bf16x3 GEMM via mma.sync + cp.async. 128x128 CTA tile, 8 warps (64x32 warp
// tiles), K-chunk 32, 2-stage SMEM double buffer, pure-bf16 loads.
// SMEM tile: [128 rows][40 halves] (80B pitch, conflict-free ldmatrix).
// Stage = Ah | Al | Bh | Bl, each 10240 B.
// mode 0: C = x @ w_qkv^T (pre-split), scatter fp32 into g_q/g_k/g_v
// mode 1: C = O @ w_fc^T + b_fc, O hi/lo gathered from g_ohi/g_olo, write out
// ---------------------------------------------------------------------------
#define KCH        32
#define NCH        (DMODEL / KCH)        // 32
#define PITCH_B    80                    // bytes per smem row
#define TILE_B     (128 * PITCH_B)       // 10240
#define STAGE_B    (4 * TILE_B)          // 40960
#define DSMEM_BYTES (2 * STAGE_B)        // 81920

__global__ __launch_bounds__(256, 2) void gemm_bf16x3_kernel(
    const __nv_bfloat16* __restrict__ Ah, const __nv_bfloat16* __restrict__ Al,
    const __nv_bfloat16* __restrict__ Bh, const __nv_bfloat16* __restrict__ Bl,
    const float* __restrict__ bias, float* __restrict__ out, int mode)
{
    extern __shared__ __align__(128) char dsm[];
    const uint32_t sbase = smem_u32(dsm);

    const int tid  = threadIdx.x;
    const int lane = tid & 31;
    const int warp = tid >> 5;
    const int bm = blockIdx.y * 128;
    const int bn = blockIdx.x * 128;
    const int warp_m = (warp >> 2) << 6;   // 0 or 64
    const int warp_n = (warp & 3) << 5;    // 0,32,64,96

    float acc[4][4][4];
#pragma unroll
    for (int i = 0; i < 4; i++)
#pragma unroll
        for (int j = 0; j < 4; j++)
#pragma unroll
            for (int r = 0; r < 4; r++) acc[i][j][r] = 0.f;

    // ---- async load of chunk c into stage st ----
    // 512 transfers of 16B per tile; 256 threads -> 2 per thread per tile.
    auto issue_chunk = [&](int c, int st) {
        const uint32_t stg = sbase + st * STAGE_B;
#pragma unroll
        for (int p = 0; p < 2; ++p) {
            const int id  = tid + (p << 8);
            const int row = id >> 2;         // 0..127
            const int seg = id & 3;          // 16B segment (8 halves)
            const uint32_t dst = stg + row * PITCH_B + (seg << 4);
            long aoff;
            if (mode == 0) {
                aoff = (long)(bm + row) * DMODEL + (c << 5) + (seg << 3);
            } else {
                const int m = bm + row;
                aoff = ((long)(((m >> 11) << 4) + (c >> 1)) * SEQ + (m & (SEQ - 1)))
                           * DHEAD + ((c & 1) << 5) + (seg << 3);
            }
            const long boff = (long)(bn + row) * DMODEL + (c << 5) + (seg << 3);
            CP_ASYNC16(dst,              Ah + aoff);
            CP_ASYNC16(dst + TILE_B,     Al + aoff);
            CP_ASYNC16(dst + 2 * TILE_B, Bh + boff);
            CP_ASYNC16(dst + 3 * TILE_B, Bl + boff);
        }
        CP_COMMIT();
    };

    issue_chunk(0, 0);

    const uint32_t lrow16 = lane & 15;
    const uint32_t lcol16 = (lane >> 4) << 4;   // 0 or 16 bytes

    for (int c = 0; c < NCH; ++c) {
        const int st = c & 1;
        if (c + 1 < NCH) {
            issue_chunk(c + 1, st ^ 1);
            CP_WAIT(1);
        } else {
            CP_WAIT(0);
        }
        __syncthreads();

        const uint32_t sa = sbase + st * STAGE_B;
        const uint32_t sb = sa + 2 * TILE_B;

#pragma unroll
        for (int kh = 0; kh < 2; ++kh) {
            uint32_t ah[4][4], al[4][4], bh[4][2], bl[4][2];
#pragma unroll
            for (int mi = 0; mi < 4; ++mi) {
                const uint32_t ad = sa + (warp_m + (mi << 4) + lrow16) * PITCH_B
                                    + (kh << 5) + lcol16;
                LDSM_X4(ah[mi][0], ah[mi][1], ah[mi][2], ah[mi][3], ad);
                LDSM_X4(al[mi][0], al[mi][1], al[mi][2], al[mi][3], ad + TILE_B);
            }
#pragma unroll
            for (int g = 0; g < 2; ++g) {
                const uint32_t bd = sb + (warp_n + (g << 4) + lrow16) * PITCH_B
                                    + (kh << 5) + lcol16;
                uint32_t t0, t1, t2, t3;
                LDSM_X4(t0, t1, t2, t3, bd);
                bh[g * 2][0] = t0;     bh[g * 2][1] = t2;
                bh[g * 2 + 1][0] = t1; bh[g * 2 + 1][1] = t3;
                LDSM_X4(t0, t1, t2, t3, bd + TILE_B);
                bl[g * 2][0] = t0;     bl[g * 2][1] = t2;
                bl[g * 2 + 1][0] = t1; bl[g * 2 + 1][1] = t3;
            }
#pragma unroll
            for (int mi = 0; mi < 4; ++mi)
#pragma unroll
                for (int nj = 0; nj < 4; ++nj) {
                    mma_bf16(acc[mi][nj], ah[mi], bh[nj][0], bh[nj][1]);
                    mma_bf16(acc[mi][nj], ah[mi], bl[nj][0], bl[nj][1]);
                    mma_bf16(acc[mi][nj], al[mi], bh[nj][0], bh[nj][1]);
                }
        }
        __syncthreads();   // stage st fully consumed before it is refilled
    }

    // ---- epilogue ----
    const int er = lane >> 2;          // 0..7
    const int ec = (lane & 3) << 1;    // 0,2,4,6
#pragma unroll
    for (int mi = 0; mi < 4; ++mi) {
#pragma unroll
        for (int nj = 0; nj < 4; ++nj) {
            const int m = bm + warp_m + (mi << 4) + er;
            const int n = bn + warp_n + (nj << 3) + ec;
            if (mode == 0) {
                const int bb = m >> 11;
                const int ss = m & (SEQ - 1);
                const int sec = n >> 10;
                const int e = n & (DMODEL - 1);
                const int h = e >> 6;
                const int dh = e & 63;
                float* dst = (sec == 0 ? g_q : (sec == 1 ? g_k : g_v))
                             + ((bb * NHEAD + h) * SEQ + ss) * DHEAD + dh;
                *(float2*)dst = make_float2(acc[mi][nj][0], acc[mi][nj][1]);
                *(float2*)(dst + 8 * DHEAD) = make_float2(acc[mi][nj][2], acc[mi][nj][3]);
            } else {
                const float2 bv = *(const float2*)(bias + n);
                float* dst = out + (long)m * DMODEL + n;
                *(float2*)dst = make_float2(acc[mi][nj][0] + bv.x, acc[mi][nj][1] + bv.y);
                *(float2*)(dst + 8 * DMODEL) =
                    make_float2(acc[mi][nj][2] + bv.x, acc[mi][nj][3] + bv.y);
            }
        }
    }
}

// ---------------------------------------------------------------------------
// Attention: flash-style online softmax over a Gaussian-banded key window.
// fp32 SIMT; epilogue now emits O as bf16 hi/lo for the proj GEMM.
// ---------------------------------------------------------------------------
__global__ __launch_bounds__(256) void attn_kernel(
    const int* __restrict__ mask, const int* __restrict__ use_g_p,
    const float* __restrict__ shift_p, const float* __restrict__ bias_pp)
{
    __shared__ float Qt[DHEAD][64];
    __shared__ float Kt[DHEAD][32];
    __shared__ float Vs[32][DHEAD];
    __shared__ float Pt[32][65];
    __shared__ float msk[32];

    const int bh = blockIdx.y;
    const int bb = bh >> 4;
    const int q0 = blockIdx.x * 64;
    const int tid = threadIdx.x;
    const int tx = tid & 15;
    const int ty = tid >> 4;

    const float shift = shift_p[0];
    const float biasv = bias_pp[0];
    const int   useg  = use_g_p[0];
    const float sh_eff = useg ? shift : 0.f;
    const float b_eff  = useg ? biasv : 0.f;

    int klo = 0, khi = SEQ;
    if (useg) {
        const int Wi = (int)sqrtf(100.f / shift) + 66;
        klo = q0 - Wi;       if (klo < 0)   klo = 0;   klo &= ~31;
        khi = q0 + 64 + Wi;  if (khi > SEQ) khi = SEQ; khi = (khi + 31) & ~31;
        if (khi > SEQ) khi = SEQ;
    }

    {
        const float* qp = g_q + (bh * SEQ + q0) * DHEAD;
        const int r  = tid & 63;
        const int u0 = tid >> 6;
#pragma unroll
        for (int u = u0; u < 16; u += 4) {
            float4 qv = *(const float4*)(qp + r * DHEAD + u * 4);
            Qt[u*4+0][r] = qv.x; Qt[u*4+1][r] = qv.y;
            Qt[u*4+2][r] = qv.z; Qt[u*4+3][r] = qv.w;
        }
    }

    float m_i[4], l_i[4], oacc[4][4];
#pragma unroll
    for (int i = 0; i < 4; i++) {
        m_i[i] = -1e30f; l_i[i] = 0.f;
#pragma unroll
        for (int j = 0; j < 4; j++) oacc[i][j] = 0.f;
    }

    const float* kbase = g_k + bh * SEQ * DHEAD;
    const float* vbase = g_v + bh * SEQ * DHEAD;
    const int*   mbase = mask + bb * SEQ;

    for (int kt = klo; kt < khi; kt += 32) {
        __syncthreads();
        {
            const int c  = tid & 31;
            const int u0 = tid >> 5;
            const float* kp = kbase + (kt + c) * DHEAD;
#pragma unroll
            for (int u = u0; u < 16; u += 8) {
                float4 kv = *(const float4*)(kp + u * 4);
                Kt[u*4+0][c] = kv.x; Kt[u*4+1][c] = kv.y;
                Kt[u*4+2][c] = kv.z; Kt[u*4+3][c] = kv.w;
            }
        }
        {
            int f = tid;
#pragma unroll
            for (int it = 0; it < 2; it++, f += 256) {
                const int r  = f >> 4;
                const int cc = (f & 15) << 2;
                *(float4*)&Vs[r][cc] = *(const float4*)(vbase + (kt + r) * DHEAD + cc);
            }
        }
        if (tid < 32) msk[tid] = (mbase[kt + tid] != 0) ? 0.f : -1e30f;
        __syncthreads();

        float sacc[4][2];
#pragma unroll
        for (int i = 0; i < 4; i++) { sacc[i][0] = 0.f; sacc[i][1] = 0.f; }
#pragma unroll
        for (int d = 0; d < DHEAD; d++) {
            float4 aq = *(const float4*)&Qt[d][ty * 4];
            float2 ak = *(const float2*)&Kt[d][tx * 2];
            sacc[0][0] += aq.x * ak.x; sacc[0][1] += aq.x * ak.y;
            sacc[1][0] += aq.y * ak.x; sacc[1][1] += aq.y * ak.y;
            sacc[2][0] += aq.z * ak.x; sacc[2][1] += aq.z * ak.y;
            sacc[3][0] += aq.w * ak.x; sacc[3][1] += aq.w * ak.y;
        }
#pragma unroll
        for (int i = 0; i < 4; i++) {
            const int qi = q0 + ty * 4 + i;
#pragma unroll
            for (int j = 0; j < 2; j++) {
                const int kj = kt + tx * 2 + j;
                const float dd = (float)(qi - kj);
                sacc[i][j] = sacc[i][j] * 0.125f + msk[tx*2+j] - (sh_eff * dd * dd + b_eff);
            }
        }
#pragma unroll
        for (int i = 0; i < 4; i++) {
            float mx = fmaxf(sacc[i][0], sacc[i][1]);
#pragma unroll
            for (int off = 8; off > 0; off >>= 1)
                mx = fmaxf(mx, __shfl_xor_sync(0xffffffffu, mx, off));
            const float mnew = fmaxf(m_i[i], mx);
            const float corr = __expf(m_i[i] - mnew);
            m_i[i] = mnew;
            float rs = 0.f;
#pragma unroll
            for (int j = 0; j < 2; j++) {
                const float p = __expf(sacc[i][j] - mnew);
                sacc[i][j] = p;
                rs += p;
            }
#pragma unroll
            for (int off = 8; off > 0; off >>= 1)
                rs += __shfl_xor_sync(0xffffffffu, rs, off);
            l_i[i] = l_i[i] * corr + rs;
#pragma unroll
            for (int j = 0; j < 4; j++) oacc[i][j] *= corr;
        }
#pragma unroll
        for (int i = 0; i < 4; i++)
#pragma unroll
            for (int j = 0; j < 2; j++)
                Pt[tx*2+j][ty*4+i] = sacc[i][j];
        __syncthreads();
#pragma unroll
        for (int c = 0; c < 32; c++) {
            const float pa0 = Pt[c][ty*4+0];
            const float pa1 = Pt[c][ty*4+1];
            const float pa2 = Pt[c][ty*4+2];
            const float pa3 = Pt[c][ty*4+3];
            float4 bv = *(const float4*)&Vs[c][tx * 4];
            oacc[0][0] += pa0*bv.x; oacc[0][1] += pa0*bv.y; oacc[0][2] += pa0*bv.z; oacc[0][3] += pa0*bv.w;
            oacc[1][0] += pa1*bv.x; oacc[1][1] += pa1*bv.y; oacc[1][2] += pa1*bv.z; oacc[1][3] += pa1*bv.w;
            oacc[2][0] += pa2*bv.x; oacc[2][1] += pa2*bv.y; oacc[2][2] += pa2*bv.z; oacc[2][3] += pa2*bv.w;
            oacc[3][0] += pa3*bv.x; oacc[3][1] += pa3*bv.y; oacc[3][2] += pa3*bv.z; oacc[3][3] += pa3*bv.w;
        }
    }

    // Normalize, split into bf16 hi/lo, write O
    const long obase = (long)(bh * SEQ + q0) * DHEAD;
#pragma unroll
    for (int i = 0; i < 4; i++) {
        const float inv = 1.f / l_i[i];
        float4 ov;
        ov.x = oacc[i][0] * inv; ov.y = oacc[i][1] * inv;
        ov.z = oacc[i][2] * inv; ov.w = oacc[i][3] * inv;
        uint2 hi, lo;
        split4(ov, hi, lo);
        const long idx = obase + (long)(ty * 4 + i) * DHEAD + tx * 4;
        *(uint2*)(g_ohi + idx) = hi;
        *(uint2*)(g_olo + idx) = lo;
    }
}

// ---------------------------------------------------------------------------
extern "C" void kernel_launch(void* const* d_in, const int* in_sizes, int n_in,
                              void* d_out, int out_size)
{
    const float* x      = (const float*)d_in[0];
    const int*   mask   = (const int*)  d_in[1];
    // d_in[2] = qmask (unused by reference)
    const int*   useg   = (const int*)  d_in[3];
    const float* w_qkv  = (const float*)d_in[4];
    const float* w_fc   = (const float*)d_in[5];
    const float* b_fc   = (const float*)d_in[6];
    const float* shift  = (const float*)d_in[7];
    const float* bias_p = (const float*)d_in[8];
    float* out = (float*)d_out;

    static bool attr_set = false;
    if (!attr_set) {
        cudaFuncSetAttribute(gemm_bf16x3_kernel,
                             cudaFuncAttributeMaxDynamicSharedMemorySize, DSMEM_BYTES);
        attr_set = true;
    }

    __nv_bfloat16 *xh, *xl, *wqh, *wql, *wfh, *wfl;
    cudaGetSymbolAddress((void**)&xh,  g_xh);
    cudaGetSymbolAddress((void**)&xl,  g_xl);
    cudaGetSymbolAddress((void**)&wqh, g_wqh);
    cudaGetSymbolAddress((void**)&wql, g_wql);
    cudaGetSymbolAddress((void**)&wfh, g_wfh);
    cudaGetSymbolAddress((void**)&wfl, g_wfl);
    __nv_bfloat16 *ohi, *olo;
    cudaGetSymbolAddress((void**)&ohi, g_ohi);
    cudaGetSymbolAddress((void**)&olo, g_olo);

    // Pre-split fp32 -> bf16 hi/lo (bandwidth-bound)
    const int n4x = MTOT * DMODEL / 4;
    const int n4q = NQKV * DMODEL / 4;
    const int n4f = DMODEL * DMODEL / 4;
    split_kernel<<<2048, 256>>>((const float4*)x,     (uint2*)xh,  (uint2*)xl,  n4x);
    split_kernel<<<2048, 256>>>((const float4*)w_qkv, (uint2*)wqh, (uint2*)wql, n4q);
    split_kernel<<<1024, 256>>>((const float4*)w_fc,  (uint2*)wfh, (uint2*)wfl, n4f);

    gemm_bf16x3_kernel<<<dim3(NQKV / 128, MTOT / 128), 256, DSMEM_BYTES>>>(
        xh, xl, wqh, wql, nullptr, nullptr, 0);
    attn_kernel<<<dim3(SEQ / 64, BHD), 256>>>(mask, useg, shift, bias_p);
    gemm_bf16x3_kernel<<<dim3(DMODEL / 128, MTOT / 128), 256, DSMEM_BYTES>>>(
        ohi, olo, wfh, wfl, b_fc, out, 1);
}

// round 5
// speedup vs baseline: 2.9921x; 1.2659x over previous
#include <cuda_runtime.h>
#include <cuda_bf16.h>
#include <math.h>
#include <stdint.h>

// Problem constants (fixed by setup_inputs)
#define BATCH 4
#define SEQ   2048
#define DMODEL 1024
#define NHEAD 16
#define DHEAD 64
#define BHD   (BATCH * NHEAD)          // 64
#define MTOT  (BATCH * SEQ)            // 8192
#define NQKV  (3 * DMODEL)             // 3072

// Scratch (sanctioned: __device__ globals, no runtime allocation)
// q/k/v stored as bf16 hi/lo in [b,h,s,dh] layout (written by qkv GEMM epilogue)
__device__ __align__(128) __nv_bfloat16 g_qh[BHD * SEQ * DHEAD];
__device__ __align__(128) __nv_bfloat16 g_ql[BHD * SEQ * DHEAD];
__device__ __align__(128) __nv_bfloat16 g_kh[BHD * SEQ * DHEAD];
__device__ __align__(128) __nv_bfloat16 g_kl[BHD * SEQ * DHEAD];
__device__ __align__(128) __nv_bfloat16 g_vh[BHD * SEQ * DHEAD];
__device__ __align__(128) __nv_bfloat16 g_vl[BHD * SEQ * DHEAD];
// attention output, bf16 hi/lo (input to proj GEMM)
__device__ __align__(128) __nv_bfloat16 g_ohi[BHD * SEQ * DHEAD];
__device__ __align__(128) __nv_bfloat16 g_olo[BHD * SEQ * DHEAD];
// pre-split GEMM operands
__device__ __align__(128) __nv_bfloat16 g_xh[MTOT * DMODEL];
__device__ __align__(128) __nv_bfloat16 g_xl[MTOT * DMODEL];
__device__ __align__(128) __nv_bfloat16 g_wqh[NQKV * DMODEL];
__device__ __align__(128) __nv_bfloat16 g_wql[NQKV * DMODEL];
__device__ __align__(128) __nv_bfloat16 g_wfh[DMODEL * DMODEL];
__device__ __align__(128) __nv_bfloat16 g_wfl[DMODEL * DMODEL];

// ---------------------------------------------------------------------------
// helpers
// ---------------------------------------------------------------------------
__device__ __forceinline__ uint32_t smem_u32(const void* p) {
    uint32_t a;
    asm("{ .reg .u64 t; cvta.to.shared.u64 t, %1; cvt.u32.u64 %0, t; }"
        : "=r"(a) : "l"(p));
    return a;
}

#define LDSM_X4(r0, r1, r2, r3, addr)                                       \
    asm volatile("ldmatrix.sync.aligned.m8n8.x4.shared.b16 {%0,%1,%2,%3}, [%4];" \
                 : "=r"(r0), "=r"(r1), "=r"(r2), "=r"(r3) : "r"(addr))

#define LDSM_X4_T(r0, r1, r2, r3, addr)                                     \
    asm volatile("ldmatrix.sync.aligned.m8n8.x4.trans.shared.b16 {%0,%1,%2,%3}, [%4];" \
                 : "=r"(r0), "=r"(r1), "=r"(r2), "=r"(r3) : "r"(addr))

__device__ __forceinline__ void mma_bf16(float* d, const uint32_t* a,
                                         uint32_t b0, uint32_t b1) {
    asm volatile(
        "mma.sync.aligned.m16n8k16.row.col.f32.bf16.bf16.f32 "
        "{%0,%1,%2,%3}, {%4,%5,%6,%7}, {%8,%9}, {%0,%1,%2,%3};"
        : "+f"(d[0]), "+f"(d[1]), "+f"(d[2]), "+f"(d[3])
        : "r"(a[0]), "r"(a[1]), "r"(a[2]), "r"(a[3]), "r"(b0), "r"(b1));
}

#define CP_ASYNC16(dst, src) \
    asm volatile("cp.async.cg.shared.global [%0], [%1], 16;" \
                 :: "r"(dst), "l"(src) : "memory")
#define CP_COMMIT()  asm volatile("cp.async.commit_group;" ::: "memory")
#define CP_WAIT(n)   asm volatile("cp.async.wait_group %0;" :: "n"(n) : "memory")

__device__ __forceinline__ void split4(float4 v, uint2& hi, uint2& lo) {
    __nv_bfloat162 h01 = __floats2bfloat162_rn(v.x, v.y);
    __nv_bfloat162 h23 = __floats2bfloat162_rn(v.z, v.w);
    __nv_bfloat162 l01 = __floats2bfloat162_rn(v.x - __bfloat162float(h01.x),
                                               v.y - __bfloat162float(h01.y));
    __nv_bfloat162 l23 = __floats2bfloat162_rn(v.z - __bfloat162float(h23.x),
                                               v.w - __bfloat162float(h23.y));
    hi.x = *(uint32_t*)&h01; hi.y = *(uint32_t*)&h23;
    lo.x = *(uint32_t*)&l01; lo.y = *(uint32_t*)&l23;
}

__device__ __forceinline__ void split2(float a, float b, uint32_t& hi, uint32_t& lo) {
    __nv_bfloat162 h = __floats2bfloat162_rn(a, b);
    __nv_bfloat162 l = __floats2bfloat162_rn(a - __bfloat162float(h.x),
                                             b - __bfloat162float(h.y));
    hi = *(uint32_t*)&h; lo = *(uint32_t*)&l;
}

// exp2 via magic-number rounding + deg-5 Taylor + exponent-bit add.
// Valid for x <= ~0.5 (we always call with x <= 0); clamps at -80 (no denormals).
__device__ __forceinline__ float exp2_poly(float x) {
    x = fmaxf(x, -80.0f);
    float t = x + 12582912.0f;           // 1.5 * 2^23: round-to-nearest-int
    float fn = t - 12582912.0f;
    float f = x - fn;                    // f in [-0.5, 0.5]
    float p = 1.3333558e-3f;
    p = fmaf(p, f, 9.6181291e-3f);
    p = fmaf(p, f, 5.5504109e-2f);
    p = fmaf(p, f, 2.4022651e-1f);
    p = fmaf(p, f, 6.9314718e-1f);
    p = fmaf(p, f, 1.0f);
    int n = (__float_as_int(t) & 0x7FFFFF) - 0x400000;
    return __int_as_float(__float_as_int(p) + (n << 23));
}

// ---------------------------------------------------------------------------
// Pre-pass: split fp32 array into bf16 hi/lo (bandwidth-bound)
// ---------------------------------------------------------------------------
__global__ __launch_bounds__(256) void split_kernel(
    const float4* __restrict__ src, uint2* __restrict__ hi,
    uint2* __restrict__ lo, int n4)
{
    for (int i = blockIdx.x * blockDim.x + threadIdx.x; i < n4;
         i += gridDim.x * blockDim.x) {
        uint2 h, l;
        split4(src[i], h, l);
        hi[i] = h;
        lo[i] = l;
    }
}

// ---------------------------------------------------------------------------
// bf16x3 GEMM via mma.sync + cp.async. 128x128 CTA tile, 8 warps (64x32 warp
// tiles), K-chunk 32, 2-stage SMEM double buffer.
// mode 0: C = x @ w_qkv^T, scatter bf16 hi/lo into g_{q,k,v}{h,l} [b,h,s,dh]
// mode 1: C = O @ w_fc^T + b_fc, O hi/lo gathered from g_ohi/g_olo, write out
// ---------------------------------------------------------------------------
#define KCH        32
#define NCH        (DMODEL / KCH)        // 32
#define PITCH_B    80                    // bytes per smem row
#define TILE_B     (128 * PITCH_B)       // 10240
#define STAGE_B    (4 * TILE_B)          // 40960
#define DSMEM_BYTES (2 * STAGE_B)        // 81920

__global__ __launch_bounds__(256, 2) void gemm_bf16x3_kernel(
    const __nv_bfloat16* __restrict__ Ah, const __nv_bfloat16* __restrict__ Al,
    const __nv_bfloat16* __restrict__ Bh, const __nv_bfloat16* __restrict__ Bl,
    const float* __restrict__ bias, float* __restrict__ out, int mode)
{
    extern __shared__ __align__(128) char dsm[];
    const uint32_t sbase = smem_u32(dsm);

    const int tid  = threadIdx.x;
    const int lane = tid & 31;
    const int warp = tid >> 5;
    const int bm = blockIdx.y * 128;
    const int bn = blockIdx.x * 128;
    const int warp_m = (warp >> 2) << 6;   // 0 or 64
    const int warp_n = (warp & 3) << 5;    // 0,32,64,96

    float acc[4][4][4];
#pragma unroll
    for (int i = 0; i < 4; i++)
#pragma unroll
        for (int j = 0; j < 4; j++)
#pragma unroll
            for (int r = 0; r < 4; r++) acc[i][j][r] = 0.f;

    auto issue_chunk = [&](int c, int st) {
        const uint32_t stg = sbase + st * STAGE_B;
#pragma unroll
        for (int p = 0; p < 2; ++p) {
            const int id  = tid + (p << 8);
            const int row = id >> 2;         // 0..127
            const int seg = id & 3;          // 16B segment (8 halves)
            const uint32_t dst = stg + row * PITCH_B + (seg << 4);
            long aoff;
            if (mode == 0) {
                aoff = (long)(bm + row) * DMODEL + (c << 5) + (seg << 3);
            } else {
                const int m = bm + row;
                aoff = ((long)(((m >> 11) << 4) + (c >> 1)) * SEQ + (m & (SEQ - 1)))
                           * DHEAD + ((c & 1) << 5) + (seg << 3);
            }
            const long boff = (long)(bn + row) * DMODEL + (c << 5) + (seg << 3);
            CP_ASYNC16(dst,              Ah + aoff);
            CP_ASYNC16(dst + TILE_B,     Al + aoff);
            CP_ASYNC16(dst + 2 * TILE_B, Bh + boff);
            CP_ASYNC16(dst + 3 * TILE_B, Bl + boff);
        }
        CP_COMMIT();
    };

    issue_chunk(0, 0);

    const uint32_t lrow16 = lane & 15;
    const uint32_t lcol16 = (lane >> 4) << 4;   // 0 or 16 bytes

    for (int c = 0; c < NCH; ++c) {
        const int st = c & 1;
        if (c + 1 < NCH) {
            issue_chunk(c + 1, st ^ 1);
            CP_WAIT(1);
        } else {
            CP_WAIT(0);
        }
        __syncthreads();

        const uint32_t sa = sbase + st * STAGE_B;
        const uint32_t sb = sa + 2 * TILE_B;

#pragma unroll
        for (int kh = 0; kh < 2; ++kh) {
            uint32_t ah[4][4], al[4][4], bh[4][2], bl[4][2];
#pragma unroll
            for (int mi = 0; mi < 4; ++mi) {
                const uint32_t ad = sa + (warp_m + (mi << 4) + lrow16) * PITCH_B
                                    + (kh << 5) + lcol16;
                LDSM_X4(ah[mi][0], ah[mi][1], ah[mi][2], ah[mi][3], ad);
                LDSM_X4(al[mi][0], al[mi][1], al[mi][2], al[mi][3], ad + TILE_B);
            }
#pragma unroll
            for (int g = 0; g < 2; ++g) {
                const uint32_t bd = sb + (warp_n + (g << 4) + lrow16) * PITCH_B
                                    + (kh << 5) + lcol16;
                uint32_t t0, t1, t2, t3;
                LDSM_X4(t0, t1, t2, t3, bd);
                bh[g * 2][0] = t0;     bh[g * 2][1] = t2;
                bh[g * 2 + 1][0] = t1; bh[g * 2 + 1][1] = t3;
                LDSM_X4(t0, t1, t2, t3, bd + TILE_B);
                bl[g * 2][0] = t0;     bl[g * 2][1] = t2;
                bl[g * 2 + 1][0] = t1; bl[g * 2 + 1][1] = t3;
            }
#pragma unroll
            for (int mi = 0; mi < 4; ++mi)
#pragma unroll
                for (int nj = 0; nj < 4; ++nj) {
                    mma_bf16(acc[mi][nj], ah[mi], bh[nj][0], bh[nj][1]);
                    mma_bf16(acc[mi][nj], ah[mi], bl[nj][0], bl[nj][1]);
                    mma_bf16(acc[mi][nj], al[mi], bh[nj][0], bh[nj][1]);
                }
        }
        __syncthreads();
    }

    // ---- epilogue ----
    const int er = lane >> 2;          // 0..7
    const int ec = (lane & 3) << 1;    // 0,2,4,6
#pragma unroll
    for (int mi = 0; mi < 4; ++mi) {
#pragma unroll
        for (int nj = 0; nj < 4; ++nj) {
            const int m = bm + warp_m + (mi << 4) + er;
            const int n = bn + warp_n + (nj << 3) + ec;
            if (mode == 0) {
                const int bb = m >> 11;
                const int ss = m & (SEQ - 1);
                const int sec = n >> 10;
                const int e = n & (DMODEL - 1);
                const int h = e >> 6;
                const int dh = e & 63;
                __nv_bfloat16 *dsth, *dstl;
                if (sec == 0)      { dsth = g_qh; dstl = g_ql; }
                else if (sec == 1) { dsth = g_kh; dstl = g_kl; }
                else               { dsth = g_vh; dstl = g_vl; }
                const long idx = ((long)(bb * NHEAD + h) * SEQ + ss) * DHEAD + dh;
                uint32_t hi, lo;
                split2(acc[mi][nj][0], acc[mi][nj][1], hi, lo);
                *(uint32_t*)(dsth + idx) = hi;
                *(uint32_t*)(dstl + idx) = lo;
                split2(acc[mi][nj][2], acc[mi][nj][3], hi, lo);
                *(uint32_t*)(dsth + idx + 8 * DHEAD) = hi;
                *(uint32_t*)(dstl + idx + 8 * DHEAD) = lo;
            } else {
                const float2 bv = *(const float2*)(bias + n);
                float* dst = out + (long)m * DMODEL + n;
                *(float2*)dst = make_float2(acc[mi][nj][0] + bv.x, acc[mi][nj][1] + bv.y);
                *(float2*)(dst + 8 * DMODEL) =
                    make_float2(acc[mi][nj][2] + bv.x, acc[mi][nj][3] + bv.y);
            }
        }
    }
}

// ---------------------------------------------------------------------------
// Attention via mma.sync: 64 queries/CTA, key tiles of 64, 4 warps.
// Warp w owns S/O rows 16w..16w+15. QK 3-pass bf16, PV 3-pass bf16.
// Softmax in log2 domain with FFMA exp2 poly (no MUFU).
// ---------------------------------------------------------------------------
#define APITCH 144                          // 72 halves per smem row
#define ATILE  (64 * APITCH)                // 9216 bytes per tensor tile
#define ASMEM  (6 * ATILE + 256)            // QH QL KH KL VH VL + mask

__global__ __launch_bounds__(128) void attn_mma_kernel(
    const int* __restrict__ mask, const int* __restrict__ use_g_p,
    const float* __restrict__ shift_p, const float* __restrict__ bias_pp)
{
    extern __shared__ __align__(128) char asmem[];
    const uint32_t QH = smem_u32(asmem);
    const uint32_t KH = QH + 2 * ATILE;
    const uint32_t VH = QH + 4 * ATILE;
    float* msk_s = (float*)(asmem + 6 * ATILE);

    const int bh = blockIdx.y;
    const int bb = bh >> 4;
    const int q0 = blockIdx.x * 64;
    const int tid  = threadIdx.x;
    const int lane = tid & 31;
    const int warp = tid >> 5;

    const float LOG2E = 1.4426950408889634f;
    const float shift = shift_p[0];
    const int   useg  = use_g_p[0];
    const float sg = useg ? shift * LOG2E : 0.f;
    const float bg = useg ? bias_pp[0] * LOG2E : 0.f;
    const float SCL = 0.125f * LOG2E;

    int klo = 0, khi = SEQ;
    if (useg) {
        const int Wi = (int)sqrtf(44.f / shift) + 50;
        klo = q0 - Wi;            if (klo < 0)   klo = 0;   klo &= ~63;
        khi = (q0 + 64 + Wi + 63) & ~63;
        if (khi > SEQ) khi = SEQ;
    }

    // ---- load Q tile (hi/lo) ----
    const long qgb = (long)(bh * SEQ + q0) * DHEAD;
    for (int i = tid; i < 512; i += 128) {
        const int r = i >> 3, ch = (i & 7) << 4;   // byte offset in 128B row
        const uint32_t dst = QH + r * APITCH + ch;
        CP_ASYNC16(dst,         (const char*)(g_qh + qgb + r * DHEAD) + ch);
        CP_ASYNC16(dst + ATILE, (const char*)(g_ql + qgb + r * DHEAD) + ch);
    }
    CP_COMMIT();
    CP_WAIT(0);
    __syncthreads();

    // ---- Q A-frags, held in registers for all key tiles ----
    uint32_t aqh[4][4], aql[4][4];
    {
        const uint32_t ad0 = QH + (warp * 16 + (lane & 15)) * APITCH
                             + ((lane >> 4) << 4);
#pragma unroll
        for (int kk = 0; kk < 4; kk++) {
            LDSM_X4(aqh[kk][0], aqh[kk][1], aqh[kk][2], aqh[kk][3], ad0 + kk * 32);
            LDSM_X4(aql[kk][0], aql[kk][1], aql[kk][2], aql[kk][3],
                    ad0 + kk * 32 + ATILE);
        }
    }

    float o[8][4];
#pragma unroll
    for (int nb = 0; nb < 8; nb++)
#pragma unroll
        for (int r = 0; r < 4; r++) o[nb][r] = 0.f;
    float m_i[2] = {-3.0e5f, -3.0e5f};
    float l_i[2] = {0.f, 0.f};

    const int qi0 = q0 + warp * 16 + (lane >> 2);   // row of c0/c1
    const int cj0 = (lane & 3) << 1;                // col pair base within n-block

    for (int kt = klo; kt < khi; kt += 64) {
        __syncthreads();   // prior tile's K/V smem fully consumed
        // ---- load K/V tiles (hi/lo) + mask ----
        for (int i = tid; i < 512; i += 128) {
            const int r = i >> 3, ch = (i & 7) << 4;
            const long gb = (long)(bh * SEQ + kt + r) * DHEAD;
            const uint32_t kd = KH + r * APITCH + ch;
            const uint32_t vd = VH + r * APITCH + ch;
            CP_ASYNC16(kd,         (const char*)(g_kh + gb) + ch);
            CP_ASYNC16(kd + ATILE, (const char*)(g_kl + gb) + ch);
            CP_ASYNC16(vd,         (const char*)(g_vh + gb) + ch);
            CP_ASYNC16(vd + ATILE, (const char*)(g_vl + gb) + ch);
        }
        if (tid < 64) msk_s[tid] = (mask[bb * SEQ + kt + tid] != 0) ? 0.f : -1.0e5f;
        CP_COMMIT();
        CP_WAIT(0);
        __syncthreads();

        // ---- S = Q K^T (3-pass bf16) ----
        float s[8][4];
#pragma unroll
        for (int nb = 0; nb < 8; nb++)
#pragma unroll
            for (int r = 0; r < 4; r++) s[nb][r] = 0.f;

#pragma unroll
        for (int kk = 0; kk < 4; kk++) {
#pragma unroll
            for (int g = 0; g < 4; g++) {
                const uint32_t bd = KH + (g * 16 + (lane & 15)) * APITCH
                                    + kk * 32 + ((lane >> 4) << 4);
                uint32_t t0, t1, t2, t3, u0, u1, u2, u3;
                LDSM_X4(t0, t1, t2, t3, bd);
                LDSM_X4(u0, u1, u2, u3, bd + ATILE);
                mma_bf16(s[g * 2],     aqh[kk], t0, t2);
                mma_bf16(s[g * 2],     aqh[kk], u0, u2);
                mma_bf16(s[g * 2],     aql[kk], t0, t2);
                mma_bf16(s[g * 2 + 1], aqh[kk], t1, t3);
                mma_bf16(s[g * 2 + 1], aqh[kk], u1, u3);
                mma_bf16(s[g * 2 + 1], aql[kk], t1, t3);
            }
        }

        // ---- logits (log2 domain) + online softmax ----
        float mx0 = -3.0e38f, mx1 = -3.0e38f;
#pragma unroll
        for (int nb = 0; nb < 8; nb++) {
            const int kj = kt + nb * 8 + cj0;
            const float mk0 = msk_s[nb * 8 + cj0];
            const float mk1 = msk_s[nb * 8 + cj0 + 1];
            const float d00 = (float)(qi0 - kj);
            const float d01 = d00 - 1.f;
            const float d20 = d00 + 8.f;
            const float d21 = d01 + 8.f;
            s[nb][0] = fmaf(s[nb][0], SCL, mk0) - fmaf(sg * d00, d00, bg);
            s[nb][1] = fmaf(s[nb][1], SCL, mk1) - fmaf(sg * d01, d01, bg);
            s[nb][2] = fmaf(s[nb][2], SCL, mk0) - fmaf(sg * d20, d20, bg);
            s[nb][3] = fmaf(s[nb][3], SCL, mk1) - fmaf(sg * d21, d21, bg);
            mx0 = fmaxf(mx0, fmaxf(s[nb][0], s[nb][1]));
            mx1 = fmaxf(mx1, fmaxf(s[nb][2], s[nb][3]));
        }
        mx0 = fmaxf(mx0, __shfl_xor_sync(0xffffffffu, mx0, 1));
        mx0 = fmaxf(mx0, __shfl_xor_sync(0xffffffffu, mx0, 2));
        mx1 = fmaxf(mx1, __shfl_xor_sync(0xffffffffu, mx1, 1));
        mx1 = fmaxf(mx1, __shfl_xor_sync(0xffffffffu, mx1, 2));
        const float mn0 = fmaxf(m_i[0], mx0);
        const float mn1 = fmaxf(m_i[1], mx1);
        const float cr0 = exp2_poly(m_i[0] - mn0);
        const float cr1 = exp2_poly(m_i[1] - mn1);
        m_i[0] = mn0; m_i[1] = mn1;

        float rs0 = 0.f, rs1 = 0.f;
#pragma unroll
        for (int nb = 0; nb < 8; nb++) {
            s[nb][0] = exp2_poly(s[nb][0] - mn0);
            s[nb][1] = exp2_poly(s[nb][1] - mn0);
            s[nb][2] = exp2_poly(s[nb][2] - mn1);
            s[nb][3] = exp2_poly(s[nb][3] - mn1);
            rs0 += s[nb][0] + s[nb][1];
            rs1 += s[nb][2] + s[nb][3];
        }
        rs0 += __shfl_xor_sync(0xffffffffu, rs0, 1);
        rs0 += __shfl_xor_sync(0xffffffffu, rs0, 2);
        rs1 += __shfl_xor_sync(0xffffffffu, rs1, 1);
        rs1 += __shfl_xor_sync(0xffffffffu, rs1, 2);
        l_i[0] = l_i[0] * cr0 + rs0;
        l_i[1] = l_i[1] * cr1 + rs1;
#pragma unroll
        for (int nb = 0; nb < 8; nb++) {
            o[nb][0] *= cr0; o[nb][1] *= cr0;
            o[nb][2] *= cr1; o[nb][3] *= cr1;
        }

        // ---- O += P V (3-pass bf16) ----
#pragma unroll
        for (int kk = 0; kk < 4; kk++) {
            uint32_t ph[4], pl[4];
            split2(s[2 * kk][0],     s[2 * kk][1],     ph[0], pl[0]);
            split2(s[2 * kk][2],     s[2 * kk][3],     ph[1], pl[1]);
            split2(s[2 * kk + 1][0], s[2 * kk + 1][1], ph[2], pl[2]);
            split2(s[2 * kk + 1][2], s[2 * kk + 1][3], ph[3], pl[3]);
#pragma unroll
            for (int gn = 0; gn < 4; gn++) {
                const uint32_t vd = VH + (kk * 16 + (lane & 15)) * APITCH
                                    + gn * 32 + ((lane >> 4) << 4);
                uint32_t t0, t1, t2, t3, u0, u1, u2, u3;
                LDSM_X4_T(t0, t1, t2, t3, vd);
                LDSM_X4_T(u0, u1, u2, u3, vd + ATILE);
                mma_bf16(o[gn * 2],     ph, t0, t1);
                mma_bf16(o[gn * 2],     ph, u0, u1);
                mma_bf16(o[gn * 2],     pl, t0, t1);
                mma_bf16(o[gn * 2 + 1], ph, t2, t3);
                mma_bf16(o[gn * 2 + 1], ph, u2, u3);
                mma_bf16(o[gn * 2 + 1], pl, t2, t3);
            }
        }
    }

    // ---- normalize + write O as bf16 hi/lo ----
    const float inv0 = 1.f / l_i[0];
    const float inv1 = 1.f / l_i[1];
    const long ob = (long)(bh * SEQ + q0 + warp * 16 + (lane >> 2)) * DHEAD + cj0;
#pragma unroll
    for (int nb = 0; nb < 8; nb++) {
        uint32_t hi, lo;
        split2(o[nb][0] * inv0, o[nb][1] * inv0, hi, lo);
        *(uint32_t*)(g_ohi + ob + nb * 8) = hi;
        *(uint32_t*)(g_olo + ob + nb * 8) = lo;
        split2(o[nb][2] * inv1, o[nb][3] * inv1, hi, lo);
        *(uint32_t*)(g_ohi + ob + 8 * DHEAD + nb * 8) = hi;
        *(uint32_t*)(g_olo + ob + 8 * DHEAD + nb * 8) = lo;
    }
}

// ---------------------------------------------------------------------------
extern "C" void kernel_launch(void* const* d_in, const int* in_sizes, int n_in,
                              void* d_out, int out_size)
{
    const float* x      = (const float*)d_in[0];
    const int*   mask   = (const int*)  d_in[1];
    // d_in[2] = qmask (unused by reference)
    const int*   useg   = (const int*)  d_in[3];
    const float* w_qkv  = (const float*)d_in[4];
    const float* w_fc   = (const float*)d_in[5];
    const float* b_fc   = (const float*)d_in[6];
    const float* shift  = (const float*)d_in[7];
    const float* bias_p = (const float*)d_in[8];
    float* out = (float*)d_out;

    static bool attr_set = false;
    if (!attr_set) {
        cudaFuncSetAttribute(gemm_bf16x3_kernel,
                             cudaFuncAttributeMaxDynamicSharedMemorySize, DSMEM_BYTES);
        cudaFuncSetAttribute(attn_mma_kernel,
                             cudaFuncAttributeMaxDynamicSharedMemorySize, ASMEM);
        attr_set = true;
    }

    __nv_bfloat16 *xh, *xl, *wqh, *wql, *wfh, *wfl, *ohi, *olo;
    cudaGetSymbolAddress((void**)&xh,  g_xh);
    cudaGetSymbolAddress((void**)&xl,  g_xl);
    cudaGetSymbolAddress((void**)&wqh, g_wqh);
    cudaGetSymbolAddress((void**)&wql, g_wql);
    cudaGetSymbolAddress((void**)&wfh, g_wfh);
    cudaGetSymbolAddress((void**)&wfl, g_wfl);
    cudaGetSymbolAddress((void**)&ohi, g_ohi);
    cudaGetSymbolAddress((void**)&olo, g_olo);

    const int n4x = MTOT * DMODEL / 4;
    const int n4q = NQKV * DMODEL / 4;
    const int n4f = DMODEL * DMODEL / 4;
    split_kernel<<<2048, 256>>>((const float4*)x,     (uint2*)xh,  (uint2*)xl,  n4x);
    split_kernel<<<2048, 256>>>((const float4*)w_qkv, (uint2*)wqh, (uint2*)wql, n4q);
    split_kernel<<<1024, 256>>>((const float4*)w_fc,  (uint2*)wfh, (uint2*)wfl, n4f);

    gemm_bf16x3_kernel<<<dim3(NQKV / 128, MTOT / 128), 256, DSMEM_BYTES>>>(
        xh, xl, wqh, wql, nullptr, nullptr, 0);
    attn_mma_kernel<<<dim3(SEQ / 64, BHD), 128, ASMEM>>>(mask, useg, shift, bias_p);
    gemm_bf16x3_kernel<<<dim3(DMODEL / 128, MTOT / 128), 256, DSMEM_BYTES>>>(
        ohi, olo, wfh, wfl, b_fc, out, 1);
}

// round 6
// speedup vs baseline: 3.6899x; 1.2332x over previous
#include <cuda_runtime.h>
#include <cuda_bf16.h>
#include <math.h>
#include <stdint.h>

// Problem constants (fixed by setup_inputs)
#define BATCH 4
#define SEQ   2048
#define DMODEL 1024
#define NHEAD 16
#define DHEAD 64
#define BHD   (BATCH * NHEAD)          // 64
#define MTOT  (BATCH * SEQ)            // 8192
#define NQKV  (3 * DMODEL)             // 3072

// ---------------------------------------------------------------------------
// Scratch (sanctioned: __device__ globals)
// Packed GEMM operands: [k-chunk(32)][row][hi 64B | lo 64B], 16B segs swizzled
// by (seg ^ (row&7)). One (chunk,128-row) slice = contiguous 16 KB.
// ---------------------------------------------------------------------------
__device__ __align__(128) char g_xpk [(size_t)MTOT  * DMODEL * 4];
__device__ __align__(128) char g_wqpk[(size_t)NQKV  * DMODEL * 4];
__device__ __align__(128) char g_wfpk[(size_t)DMODEL* DMODEL * 4];
__device__ __align__(128) char g_opk [(size_t)MTOT  * DMODEL * 4];
// q/k/v for attention: bf16 hi/lo, [b,h,s,dh] (written by qkv GEMM epilogue)
__device__ __align__(128) __nv_bfloat16 g_qh[BHD * SEQ * DHEAD];
__device__ __align__(128) __nv_bfloat16 g_ql[BHD * SEQ * DHEAD];
__device__ __align__(128) __nv_bfloat16 g_kh[BHD * SEQ * DHEAD];
__device__ __align__(128) __nv_bfloat16 g_kl[BHD * SEQ * DHEAD];
__device__ __align__(128) __nv_bfloat16 g_vh[BHD * SEQ * DHEAD];
__device__ __align__(128) __nv_bfloat16 g_vl[BHD * SEQ * DHEAD];

// ---------------------------------------------------------------------------
// helpers
// ---------------------------------------------------------------------------
__device__ __forceinline__ uint32_t smem_u32(const void* p) {
    uint32_t a;
    asm("{ .reg .u64 t; cvta.to.shared.u64 t, %1; cvt.u32.u64 %0, t; }"
        : "=r"(a) : "l"(p));
    return a;
}

#define LDSM_X4(r0, r1, r2, r3, addr)                                       \
    asm volatile("ldmatrix.sync.aligned.m8n8.x4.shared.b16 {%0,%1,%2,%3}, [%4];" \
                 : "=r"(r0), "=r"(r1), "=r"(r2), "=r"(r3) : "r"(addr))

#define LDSM_X4_T(r0, r1, r2, r3, addr)                                     \
    asm volatile("ldmatrix.sync.aligned.m8n8.x4.trans.shared.b16 {%0,%1,%2,%3}, [%4];" \
                 : "=r"(r0), "=r"(r1), "=r"(r2), "=r"(r3) : "r"(addr))

__device__ __forceinline__ void mma_bf16(float* d, const uint32_t* a,
                                         uint32_t b0, uint32_t b1) {
    asm volatile(
        "mma.sync.aligned.m16n8k16.row.col.f32.bf16.bf16.f32 "
        "{%0,%1,%2,%3}, {%4,%5,%6,%7}, {%8,%9}, {%0,%1,%2,%3};"
        : "+f"(d[0]), "+f"(d[1]), "+f"(d[2]), "+f"(d[3])
        : "r"(a[0]), "r"(a[1]), "r"(a[2]), "r"(a[3]), "r"(b0), "r"(b1));
}

#define CP_ASYNC16(dst, src) \
    asm volatile("cp.async.cg.shared.global [%0], [%1], 16;" \
                 :: "r"(dst), "l"(src) : "memory")
#define CP_COMMIT()  asm volatile("cp.async.commit_group;" ::: "memory")
#define CP_WAIT(n)   asm volatile("cp.async.wait_group %0;" :: "n"(n) : "memory")

#define MBAR_INIT(addr, cnt) \
    asm volatile("mbarrier.init.shared.b64 [%0], %1;" :: "r"(addr), "r"((uint32_t)(cnt)) : "memory")
#define MBAR_EXPECT_TX(addr, bytes) \
    asm volatile("mbarrier.arrive.expect_tx.shared.b64 _, [%0], %1;" \
                 :: "r"(addr), "r"((uint32_t)(bytes)) : "memory")
#define BULK_G2S(dst, src, bytes, mbar) \
    asm volatile("cp.async.bulk.shared::cluster.global.mbarrier::complete_tx::bytes " \
                 "[%0], [%1], %2, [%3];" \
                 :: "r"(dst), "l"(src), "r"((uint32_t)(bytes)), "r"(mbar) : "memory")

__device__ __forceinline__ void mbar_wait(uint32_t addr, uint32_t parity) {
    asm volatile(
        "{\n\t.reg .pred P;\n\t"
        "WL%=:\n\t"
        "mbarrier.try_wait.parity.acquire.cta.shared::cta.b64 P, [%0], %1, 0x989680;\n\t"
        "@!P bra WL%=;\n\t}"
        :: "r"(addr), "r"(parity) : "memory");
}

__device__ __forceinline__ void split4(float4 v, uint2& hi, uint2& lo) {
    __nv_bfloat162 h01 = __floats2bfloat162_rn(v.x, v.y);
    __nv_bfloat162 h23 = __floats2bfloat162_rn(v.z, v.w);
    __nv_bfloat162 l01 = __floats2bfloat162_rn(v.x - __bfloat162float(h01.x),
                                               v.y - __bfloat162float(h01.y));
    __nv_bfloat162 l23 = __floats2bfloat162_rn(v.z - __bfloat162float(h23.x),
                                               v.w - __bfloat162float(h23.y));
    hi.x = *(uint32_t*)&h01; hi.y = *(uint32_t*)&h23;
    lo.x = *(uint32_t*)&l01; lo.y = *(uint32_t*)&l23;
}

__device__ __forceinline__ void split2(float a, float b, uint32_t& hi, uint32_t& lo) {
    __nv_bfloat162 h = __floats2bfloat162_rn(a, b);
    __nv_bfloat162 l = __floats2bfloat162_rn(a - __bfloat162float(h.x),
                                             b - __bfloat162float(h.y));
    hi = *(uint32_t*)&h; lo = *(uint32_t*)&l;
}

// exp2 via magic-number rounding + deg-5 poly + exponent-bit add (no MUFU).
__device__ __forceinline__ float exp2_poly(float x) {
    x = fmaxf(x, -80.0f);
    float t = x + 12582912.0f;
    float fn = t - 12582912.0f;
    float f = x - fn;
    float p = 1.3333558e-3f;
    p = fmaf(p, f, 9.6181291e-3f);
    p = fmaf(p, f, 5.5504109e-2f);
    p = fmaf(p, f, 2.4022651e-1f);
    p = fmaf(p, f, 6.9314718e-1f);
    p = fmaf(p, f, 1.0f);
    int n = (__float_as_int(t) & 0x7FFFFF) - 0x400000;
    return __int_as_float(__float_as_int(p) + (n << 23));
}

// ---------------------------------------------------------------------------
// Pre-pass: fp32 [M,1024] -> packed swizzled hi/lo chunks (bandwidth-bound)
// dst layout: chunk c (k/32), row m: 128 bytes = [hi 64B | lo 64B],
// 16B seg index XOR (m & 7).
// ---------------------------------------------------------------------------
__global__ __launch_bounds__(256) void split_pack_kernel(
    const float* __restrict__ src, char* __restrict__ dst, int M)
{
    const int total = M * 128;   // groups of 8 floats
    for (int idx = blockIdx.x * blockDim.x + threadIdx.x; idx < total;
         idx += gridDim.x * blockDim.x) {
        const int m   = idx >> 7;
        const int k   = (idx & 127) << 3;
        const int c   = k >> 5;
        const int seg = (k & 31) >> 3;   // 0..3
        const float4 v0 = *(const float4*)(src + (size_t)m * DMODEL + k);
        const float4 v1 = *(const float4*)(src + (size_t)m * DMODEL + k + 4);
        uint2 h0, l0, h1, l1;
        split4(v0, h0, l0);
        split4(v1, h1, l1);
        char* row = dst + ((size_t)c * M + m) * 128;
        const int sx = m & 7;
        *(uint4*)(row + (((seg)     ^ sx) << 4)) = make_uint4(h0.x, h0.y, h1.x, h1.y);
        *(uint4*)(row + (((seg + 4) ^ sx) << 4)) = make_uint4(l0.x, l0.y, l1.x, l1.y);
    }
}

// ---------------------------------------------------------------------------
// bf16x3 GEMM: packed operands, cp.async.bulk + mbarrier 3-stage pipeline.
// 128x128 CTA tile, 8 warps (64x32 warp tiles), K-chunk 32.
// Stage = A tile 16KB + B tile 16KB = 32KB.
// mode 0: C = x @ w_qkv^T, scatter bf16 hi/lo into g_{q,k,v}{h,l} [b,h,s,dh]
// mode 1: C = O @ w_fc^T + b_fc, write fp32 out
// ---------------------------------------------------------------------------
#define NCHK   32
#define STG_B  32768
#define DSMEM_BYTES (3 * STG_B)   // 98304

__global__ __launch_bounds__(256, 2) void gemm_pk_kernel(
    const char* __restrict__ Apk, const char* __restrict__ Bpk,
    int Mtot, int Ntot,
    const float* __restrict__ bias, float* __restrict__ out, int mode)
{
    extern __shared__ __align__(128) char dsm[];
    __shared__ __align__(8) uint64_t mbar[3];
    const uint32_t sbase = smem_u32(dsm);
    const uint32_t mb0 = smem_u32(&mbar[0]);

    const int tid  = threadIdx.x;
    const int lane = tid & 31;
    const int warp = tid >> 5;
    const int bm = blockIdx.y * 128;
    const int bn = blockIdx.x * 128;
    const int warp_m = (warp >> 2) << 6;   // 0 or 64
    const int warp_n = (warp & 3) << 5;    // 0,32,64,96

    if (tid == 0) {
        MBAR_INIT(mb0,      1);
        MBAR_INIT(mb0 + 8,  1);
        MBAR_INIT(mb0 + 16, 1);
    }
    __syncthreads();

    auto issue = [&](int c) {
        const int st = c % 3;
        const uint32_t mb = mb0 + st * 8;
        MBAR_EXPECT_TX(mb, 2 * 16384);
        BULK_G2S(sbase + st * STG_B,         Apk + ((size_t)c * Mtot + bm) * 128,
                 16384, mb);
        BULK_G2S(sbase + st * STG_B + 16384, Bpk + ((size_t)c * Ntot + bn) * 128,
                 16384, mb);
    };

    if (tid == 0) { issue(0); issue(1); }

    float acc[4][4][4];
#pragma unroll
    for (int i = 0; i < 4; i++)
#pragma unroll
        for (int j = 0; j < 4; j++)
#pragma unroll
            for (int r = 0; r < 4; r++) acc[i][j][r] = 0.f;

    const int r16 = lane & 15;
    const int cs  = lane >> 4;        // 0/1
    const int sx  = lane & 7;

    for (int c = 0; c < NCHK; ++c) {
        const int st = c % 3;
        mbar_wait(mb0 + st * 8, (c / 3) & 1);

        const uint32_t Ast = sbase + st * STG_B;
        const uint32_t Bst = Ast + 16384;

#pragma unroll
        for (int kh = 0; kh < 2; ++kh) {
            const int seg = kh * 2 + cs;           // 0..3 (hi); lo = addr ^ 64
            uint32_t ah[4][4], al[4][4], bh[4][2], bl[4][2];
#pragma unroll
            for (int mi = 0; mi < 4; ++mi) {
                const uint32_t ad = Ast + (warp_m + (mi << 4) + r16) * 128
                                    + ((seg ^ sx) << 4);
                LDSM_X4(ah[mi][0], ah[mi][1], ah[mi][2], ah[mi][3], ad);
                LDSM_X4(al[mi][0], al[mi][1], al[mi][2], al[mi][3], ad ^ 64);
            }
#pragma unroll
            for (int g = 0; g < 2; ++g) {
                const uint32_t bd = Bst + (warp_n + (g << 4) + r16) * 128
                                    + ((seg ^ sx) << 4);
                uint32_t t0, t1, t2, t3;
                LDSM_X4(t0, t1, t2, t3, bd);
                bh[g * 2][0] = t0;     bh[g * 2][1] = t2;
                bh[g * 2 + 1][0] = t1; bh[g * 2 + 1][1] = t3;
                LDSM_X4(t0, t1, t2, t3, bd ^ 64);
                bl[g * 2][0] = t0;     bl[g * 2][1] = t2;
                bl[g * 2 + 1][0] = t1; bl[g * 2 + 1][1] = t3;
            }
            // three independent sweeps (hh, hl, lh) for max ILP
#pragma unroll
            for (int mi = 0; mi < 4; ++mi)
#pragma unroll
                for (int nj = 0; nj < 4; ++nj)
                    mma_bf16(acc[mi][nj], ah[mi], bh[nj][0], bh[nj][1]);
#pragma unroll
            for (int mi = 0; mi < 4; ++mi)
#pragma unroll
                for (int nj = 0; nj < 4; ++nj)
                    mma_bf16(acc[mi][nj], ah[mi], bl[nj][0], bl[nj][1]);
#pragma unroll
            for (int mi = 0; mi < 4; ++mi)
#pragma unroll
                for (int nj = 0; nj < 4; ++nj)
                    mma_bf16(acc[mi][nj], al[mi], bh[nj][0], bh[nj][1]);
        }

        __syncthreads();                        // stage st fully consumed
        if (tid == 0 && c + 2 < NCHK) issue(c + 2);
    }

    // ---- epilogue ----
    const int er = lane >> 2;          // 0..7
    const int ec = (lane & 3) << 1;    // 0,2,4,6
#pragma unroll
    for (int mi = 0; mi < 4; ++mi) {
#pragma unroll
        for (int nj = 0; nj < 4; ++nj) {
            const int m = bm + warp_m + (mi << 4) + er;
            const int n = bn + warp_n + (nj << 3) + ec;
            if (mode == 0) {
                const int bb = m >> 11;
                const int ss = m & (SEQ - 1);
                const int sec = n >> 10;
                const int e = n & (DMODEL - 1);
                const int h = e >> 6;
                const int dh = e & 63;
                __nv_bfloat16 *dsth, *dstl;
                if (sec == 0)      { dsth = g_qh; dstl = g_ql; }
                else if (sec == 1) { dsth = g_kh; dstl = g_kl; }
                else               { dsth = g_vh; dstl = g_vl; }
                const long idx = ((long)(bb * NHEAD + h) * SEQ + ss) * DHEAD + dh;
                uint32_t hi, lo;
                split2(acc[mi][nj][0], acc[mi][nj][1], hi, lo);
                *(uint32_t*)(dsth + idx) = hi;
                *(uint32_t*)(dstl + idx) = lo;
                split2(acc[mi][nj][2], acc[mi][nj][3], hi, lo);
                *(uint32_t*)(dsth + idx + 8 * DHEAD) = hi;
                *(uint32_t*)(dstl + idx + 8 * DHEAD) = lo;
            } else {
                const float2 bv = *(const float2*)(bias + n);
                float* dst = out + (long)m * DMODEL + n;
                *(float2*)dst = make_float2(acc[mi][nj][0] + bv.x, acc[mi][nj][1] + bv.y);
                *(float2*)(dst + 8 * DMODEL) =
                    make_float2(acc[mi][nj][2] + bv.x, acc[mi][nj][3] + bv.y);
            }
        }
    }
}

// ---------------------------------------------------------------------------
// Attention via mma.sync (as round 5), epilogue writes packed-swizzled O.
// ---------------------------------------------------------------------------
#define APITCH 144
#define ATILE  (64 * APITCH)
#define ASMEM  (6 * ATILE + 256)

__global__ __launch_bounds__(128) void attn_mma_kernel(
    const int* __restrict__ mask, const int* __restrict__ use_g_p,
    const float* __restrict__ shift_p, const float* __restrict__ bias_pp)
{
    extern __shared__ __align__(128) char asmem[];
    const uint32_t QH = smem_u32(asmem);
    const uint32_t KH = QH + 2 * ATILE;
    const uint32_t VH = QH + 4 * ATILE;
    float* msk_s = (float*)(asmem + 6 * ATILE);

    const int bh = blockIdx.y;
    const int bb = bh >> 4;
    const int q0 = blockIdx.x * 64;
    const int tid  = threadIdx.x;
    const int lane = tid & 31;
    const int warp = tid >> 5;

    const float LOG2E = 1.4426950408889634f;
    const float shift = shift_p[0];
    const int   useg  = use_g_p[0];
    const float sg = useg ? shift * LOG2E : 0.f;
    const float bg = useg ? bias_pp[0] * LOG2E : 0.f;
    const float SCL = 0.125f * LOG2E;

    int klo = 0, khi = SEQ;
    if (useg) {
        const int Wi = (int)sqrtf(44.f / shift) + 50;
        klo = q0 - Wi;            if (klo < 0)   klo = 0;   klo &= ~63;
        khi = (q0 + 64 + Wi + 63) & ~63;
        if (khi > SEQ) khi = SEQ;
    }

    const long qgb = (long)(bh * SEQ + q0) * DHEAD;
    for (int i = tid; i < 512; i += 128) {
        const int r = i >> 3, ch = (i & 7) << 4;
        const uint32_t dst = QH + r * APITCH + ch;
        CP_ASYNC16(dst,         (const char*)(g_qh + qgb + r * DHEAD) + ch);
        CP_ASYNC16(dst + ATILE, (const char*)(g_ql + qgb + r * DHEAD) + ch);
    }
    CP_COMMIT();
    CP_WAIT(0);
    __syncthreads();

    uint32_t aqh[4][4], aql[4][4];
    {
        const uint32_t ad0 = QH + (warp * 16 + (lane & 15)) * APITCH
                             + ((lane >> 4) << 4);
#pragma unroll
        for (int kk = 0; kk < 4; kk++) {
            LDSM_X4(aqh[kk][0], aqh[kk][1], aqh[kk][2], aqh[kk][3], ad0 + kk * 32);
            LDSM_X4(aql[kk][0], aql[kk][1], aql[kk][2], aql[kk][3],
                    ad0 + kk * 32 + ATILE);
        }
    }

    float o[8][4];
#pragma unroll
    for (int nb = 0; nb < 8; nb++)
#pragma unroll
        for (int r = 0; r < 4; r++) o[nb][r] = 0.f;
    float m_i[2] = {-3.0e5f, -3.0e5f};
    float l_i[2] = {0.f, 0.f};

    const int qi0 = q0 + warp * 16 + (lane >> 2);
    const int cj0 = (lane & 3) << 1;

    for (int kt = klo; kt < khi; kt += 64) {
        __syncthreads();
        for (int i = tid; i < 512; i += 128) {
            const int r = i >> 3, ch = (i & 7) << 4;
            const long gb = (long)(bh * SEQ + kt + r) * DHEAD;
            const uint32_t kd = KH + r * APITCH + ch;
            const uint32_t vd = VH + r * APITCH + ch;
            CP_ASYNC16(kd,         (const char*)(g_kh + gb) + ch);
            CP_ASYNC16(kd + ATILE, (const char*)(g_kl + gb) + ch);
            CP_ASYNC16(vd,         (const char*)(g_vh + gb) + ch);
            CP_ASYNC16(vd + ATILE, (const char*)(g_vl + gb) + ch);
        }
        if (tid < 64) msk_s[tid] = (mask[bb * SEQ + kt + tid] != 0) ? 0.f : -1.0e5f;
        CP_COMMIT();
        CP_WAIT(0);
        __syncthreads();

        float s[8][4];
#pragma unroll
        for (int nb = 0; nb < 8; nb++)
#pragma unroll
            for (int r = 0; r < 4; r++) s[nb][r] = 0.f;

#pragma unroll
        for (int kk = 0; kk < 4; kk++) {
#pragma unroll
            for (int g = 0; g < 4; g++) {
                const uint32_t bd = KH + (g * 16 + (lane & 15)) * APITCH
                                    + kk * 32 + ((lane >> 4) << 4);
                uint32_t t0, t1, t2, t3, u0, u1, u2, u3;
                LDSM_X4(t0, t1, t2, t3, bd);
                LDSM_X4(u0, u1, u2, u3, bd + ATILE);
                mma_bf16(s[g * 2],     aqh[kk], t0, t2);
                mma_bf16(s[g * 2],     aqh[kk], u0, u2);
                mma_bf16(s[g * 2],     aql[kk], t0, t2);
                mma_bf16(s[g * 2 + 1], aqh[kk], t1, t3);
                mma_bf16(s[g * 2 + 1], aqh[kk], u1, u3);
                mma_bf16(s[g * 2 + 1], aql[kk], t1, t3);
            }
        }

        float mx0 = -3.0e38f, mx1 = -3.0e38f;
#pragma unroll
        for (int nb = 0; nb < 8; nb++) {
            const int kj = kt + nb * 8 + cj0;
            const float mk0 = msk_s[nb * 8 + cj0];
            const float mk1 = msk_s[nb * 8 + cj0 + 1];
            const float d00 = (float)(qi0 - kj);
            const float d01 = d00 - 1.f;
            const float d20 = d00 + 8.f;
            const float d21 = d01 + 8.f;
            s[nb][0] = fmaf(s[nb][0], SCL, mk0) - fmaf(sg * d00, d00, bg);
            s[nb][1] = fmaf(s[nb][1], SCL, mk1) - fmaf(sg * d01, d01, bg);
            s[nb][2] = fmaf(s[nb][2], SCL, mk0) - fmaf(sg * d20, d20, bg);
            s[nb][3] = fmaf(s[nb][3], SCL, mk1) - fmaf(sg * d21, d21, bg);
            mx0 = fmaxf(mx0, fmaxf(s[nb][0], s[nb][1]));
            mx1 = fmaxf(mx1, fmaxf(s[nb][2], s[nb][3]));
        }
        mx0 = fmaxf(mx0, __shfl_xor_sync(0xffffffffu, mx0, 1));
        mx0 = fmaxf(mx0, __shfl_xor_sync(0xffffffffu, mx0, 2));
        mx1 = fmaxf(mx1, __shfl_xor_sync(0xffffffffu, mx1, 1));
        mx1 = fmaxf(mx1, __shfl_xor_sync(0xffffffffu, mx1, 2));
        const float mn0 = fmaxf(m_i[0], mx0);
        const float mn1 = fmaxf(m_i[1], mx1);
        const float cr0 = exp2_poly(m_i[0] - mn0);
        const float cr1 = exp2_poly(m_i[1] - mn1);
        m_i[0] = mn0; m_i[1] = mn1;

        float rs0 = 0.f, rs1 = 0.f;
#pragma unroll
        for (int nb = 0; nb < 8; nb++) {
            s[nb][0] = exp2_poly(s[nb][0] - mn0);
            s[nb][1] = exp2_poly(s[nb][1] - mn0);
            s[nb][2] = exp2_poly(s[nb][2] - mn1);
            s[nb][3] = exp2_poly(s[nb][3] - mn1);
            rs0 += s[nb][0] + s[nb][1];
            rs1 += s[nb][2] + s[nb][3];
        }
        rs0 += __shfl_xor_sync(0xffffffffu, rs0, 1);
        rs0 += __shfl_xor_sync(0xffffffffu, rs0, 2);
        rs1 += __shfl_xor_sync(0xffffffffu, rs1, 1);
        rs1 += __shfl_xor_sync(0xffffffffu, rs1, 2);
        l_i[0] = l_i[0] * cr0 + rs0;
        l_i[1] = l_i[1] * cr1 + rs1;
#pragma unroll
        for (int nb = 0; nb < 8; nb++) {
            o[nb][0] *= cr0; o[nb][1] *= cr0;
            o[nb][2] *= cr1; o[nb][3] *= cr1;
        }

#pragma unroll
        for (int kk = 0; kk < 4; kk++) {
            uint32_t ph[4], pl[4];
            split2(s[2 * kk][0],     s[2 * kk][1],     ph[0], pl[0]);
            split2(s[2 * kk][2],     s[2 * kk][3],     ph[1], pl[1]);
            split2(s[2 * kk + 1][0], s[2 * kk + 1][1], ph[2], pl[2]);
            split2(s[2 * kk + 1][2], s[2 * kk + 1][3], ph[3], pl[3]);
#pragma unroll
            for (int gn = 0; gn < 4; gn++) {
                const uint32_t vd = VH + (kk * 16 + (lane & 15)) * APITCH
                                    + gn * 32 + ((lane >> 4) << 4);
                uint32_t t0, t1, t2, t3, u0, u1, u2, u3;
                LDSM_X4_T(t0, t1, t2, t3, vd);
                LDSM_X4_T(u0, u1, u2, u3, vd + ATILE);
                mma_bf16(o[gn * 2],     ph, t0, t1);
                mma_bf16(o[gn * 2],     ph, u0, u1);
                mma_bf16(o[gn * 2],     pl, t0, t1);
                mma_bf16(o[gn * 2 + 1], ph, t2, t3);
                mma_bf16(o[gn * 2 + 1], ph, u2, u3);
                mma_bf16(o[gn * 2 + 1], pl, t2, t3);
            }
        }
    }

    // ---- normalize + write O in packed-swizzled layout for proj GEMM ----
    const float inv0 = 1.f / l_i[0];
    const float inv1 = 1.f / l_i[1];
    const int h = bh & 15;
    const int mrow = bb * SEQ + q0 + warp * 16 + (lane >> 2);
    const int swx = mrow & 7;   // (mrow+8)&7 == mrow&7
#pragma unroll
    for (int nb = 0; nb < 8; nb++) {
        const int d0 = nb * 8 + cj0;
        const int c  = 2 * h + (d0 >> 5);
        const int kk = d0 & 31;
        const int off_hi = ((((kk >> 3)) ^ swx) << 4) + ((kk & 7) << 1);
        char* r1 = g_opk + ((size_t)c * MTOT + mrow) * 128;
        char* r2 = r1 + 8 * 128;
        uint32_t hi, lo;
        split2(o[nb][0] * inv0, o[nb][1] * inv0, hi, lo);
        *(uint32_t*)(r1 + off_hi)        = hi;
        *(uint32_t*)(r1 + (off_hi ^ 64)) = lo;
        split2(o[nb][2] * inv1, o[nb][3] * inv1, hi, lo);
        *(uint32_t*)(r2 + off_hi)        = hi;
        *(uint32_t*)(r2 + (off_hi ^ 64)) = lo;
    }
}

// ---------------------------------------------------------------------------
extern "C" void kernel_launch(void* const* d_in, const int* in_sizes, int n_in,
                              void* d_out, int out_size)
{
    const float* x      = (const float*)d_in[0];
    const int*   mask   = (const int*)  d_in[1];
    // d_in[2] = qmask (unused by reference)
    const int*   useg   = (const int*)  d_in[3];
    const float* w_qkv  = (const float*)d_in[4];
    const float* w_fc   = (const float*)d_in[5];
    const float* b_fc   = (const float*)d_in[6];
    const float* shift  = (const float*)d_in[7];
    const float* bias_p = (const float*)d_in[8];
    float* out = (float*)d_out;

    static bool attr_set = false;
    if (!attr_set) {
        cudaFuncSetAttribute(gemm_pk_kernel,
                             cudaFuncAttributeMaxDynamicSharedMemorySize, DSMEM_BYTES);
        cudaFuncSetAttribute(attn_mma_kernel,
                             cudaFuncAttributeMaxDynamicSharedMemorySize, ASMEM);
        attr_set = true;
    }

    char *xpk, *wqpk, *wfpk, *opk;
    cudaGetSymbolAddress((void**)&xpk,  g_xpk);
    cudaGetSymbolAddress((void**)&wqpk, g_wqpk);
    cudaGetSymbolAddress((void**)&wfpk, g_wfpk);
    cudaGetSymbolAddress((void**)&opk,  g_opk);

    split_pack_kernel<<<2048, 256>>>(x,     xpk,  MTOT);
    split_pack_kernel<<<768,  256>>>(w_qkv, wqpk, NQKV);
    split_pack_kernel<<<256,  256>>>(w_fc,  wfpk, DMODEL);

    gemm_pk_kernel<<<dim3(NQKV / 128, MTOT / 128), 256, DSMEM_BYTES>>>(
        xpk, wqpk, MTOT, NQKV, nullptr, nullptr, 0);
    attn_mma_kernel<<<dim3(SEQ / 64, BHD), 128, ASMEM>>>(mask, useg, shift, bias_p);
    gemm_pk_kernel<<<dim3(DMODEL / 128, MTOT / 128), 256, DSMEM_BYTES>>>(
        opk, wfpk, MTOT, DMODEL, b_fc, out, 1);
}